// round 10
// baseline (speedup 1.0000x reference)
#include <cuda_runtime.h>
#include <cstdint>

#define NNODE 21
#define NPAD 24
#define HIDD 128
#define HSTR 132            // full-width state row stride (floats), conflict-free
#define ZSTR 68             // half-width array row stride (floats), conflict-free
#define TSTEPS 500
#define NEDGE 210
#define NTHR 256
#define FHALF 64            // features per CTA (cluster of 2)
#define CHUNK_F 2048        // floats per 32-k x 64-col weight chunk

typedef unsigned long long u64;
typedef unsigned int u32;

// ---------------- packed f32x2 helpers ----------------
__device__ __forceinline__ u64 pk2(float lo, float hi) {
    u64 r; asm("mov.b64 %0,{%1,%2};" : "=l"(r) : "f"(lo), "f"(hi)); return r;
}
__device__ __forceinline__ u64 bc2(float v) {
    u64 r; asm("mov.b64 %0,{%1,%1};" : "=l"(r) : "f"(v)); return r;
}
__device__ __forceinline__ u64 fma2(u64 a, u64 b, u64 c) {
    u64 d; asm("fma.rn.f32x2 %0,%1,%2,%3;" : "=l"(d) : "l"(a), "l"(b), "l"(c)); return d;
}
__device__ __forceinline__ u64 add2(u64 a, u64 b) {
    u64 d; asm("add.rn.f32x2 %0,%1,%2;" : "=l"(d) : "l"(a), "l"(b)); return d;
}
__device__ __forceinline__ void up2(u64 v, float& lo, float& hi) {
    asm("mov.b64 {%0,%1},%2;" : "=f"(lo), "=f"(hi) : "l"(v));
}
__device__ __forceinline__ float sigm(float v) {
    return __fdividef(1.0f, 1.0f + __expf(-v));
}
__device__ __forceinline__ float tanh_(float v) {
    return 1.0f - __fdividef(2.0f, __expf(2.0f * v) + 1.0f);
}

// ---------------- cp.async helpers ----------------
__device__ __forceinline__ void cpa16(void* dst, const void* src) {
    u32 d = (u32)__cvta_generic_to_shared(dst);
    asm volatile("cp.async.cg.shared.global [%0], [%1], 16;\n" :: "r"(d), "l"(src));
}
__device__ __forceinline__ void cpcommit() { asm volatile("cp.async.commit_group;\n"); }
template <int N> __device__ __forceinline__ void cpwait() {
    asm volatile("cp.async.wait_group %0;\n" :: "n"(N));
}

// ---------------- cluster helpers ----------------
#define CLUSTER_ARRIVE() asm volatile("barrier.cluster.arrive.aligned;" ::: "memory")
#define CLUSTER_WAIT()   asm volatile("barrier.cluster.wait.aligned;" ::: "memory")

__device__ __forceinline__ u32 ctarank() {
    u32 r; asm("mov.u32 %0, %%cluster_ctarank;" : "=r"(r)); return r;
}
__device__ __forceinline__ void st_peer_u64(u32 laddr, u32 peer, u64 v) {
    u32 raddr;
    asm("mapa.shared::cluster.u32 %0, %1, %2;" : "=r"(raddr) : "r"(laddr), "r"(peer));
    asm volatile("st.shared::cluster.b64 [%0], %1;" :: "r"(raddr), "l"(v) : "memory");
}
__device__ __forceinline__ void st_peer_u32(u32 laddr, u32 peer, u32 v) {
    u32 raddr;
    asm("mapa.shared::cluster.u32 %0, %1, %2;" : "=r"(raddr) : "r"(laddr), "r"(peer));
    asm volatile("st.shared::cluster.b32 [%0], %1;" :: "r"(raddr), "r"(v) : "memory");
}
__device__ __forceinline__ u32 smem_u32(const void* p) {
    return (u32)__cvta_generic_to_shared(p);
}

// ---------------- device-global precomputed state ----------------
__device__ float g_A[NNODE * NNODE];
__device__ float g_fold1[6 * HIDD];
__device__ float g_c2[3 * HIDD];
__device__ __align__(16) float g_W2L[3 * HIDD * HIDD];

// ---------------- fused setup kernel ----------------
__global__ void setup_all(
    const int* __restrict__ ei, const float* __restrict__ ew,
    const float* Wz1, const float* bz1, const float* lzw1, const float* lzb1,
    const float* Wr1, const float* br1, const float* lrw1, const float* lrb1,
    const float* Wh1, const float* bh1, const float* lhw1, const float* lhb1,
    const float* Wz2, const float* bz2, const float* lzw2, const float* lzb2,
    const float* Wr2, const float* br2, const float* lrw2, const float* lrb2,
    const float* Wh2, const float* bh2, const float* lhw2, const float* lhb2) {
    int tid = threadIdx.x;
    if (blockIdx.x == 0) {
        __shared__ float dinv[NNODE];
        if (tid < NNODE) {
            float d = 1.0f;
            for (int e = 0; e < NEDGE; e++)
                if (ei[NEDGE + e] == tid) d += ew[e];
            dinv[tid] = (d > 0.f) ? (1.0f / sqrtf(d)) : 0.0f;
        }
        __syncthreads();
        if (tid < NNODE * NNODE) {
            int i = tid / NNODE, j = tid % NNODE;
            float a = (i == j) ? dinv[i] * dinv[i] : 0.0f;
            for (int e = 0; e < NEDGE; e++)
                if (ei[e] == j && ei[NEDGE + e] == i)
                    a += dinv[j] * ew[e] * dinv[i];
            g_A[tid] = a;
        }
        if (tid < HIDD) {
            const float* Ws[3] = {Wz1, Wr1, Wh1};
            const float* bs[3] = {bz1, br1, bh1};
            const float* ls[3] = {lzw1, lrw1, lhw1};
            const float* lb[3] = {lzb1, lrb1, lhb1};
            for (int g = 0; g < 3; g++) {
                float v = 0.f, c = 0.f;
                for (int q = 0; q < HIDD; q++) {
                    float l = ls[g][q * HIDD + tid];
                    v += Ws[g][q] * l;
                    c += bs[g][q] * l;
                }
                g_fold1[g * HIDD + tid] = v;
                g_fold1[(3 + g) * HIDD + tid] = c + lb[g][tid];
            }
            const float* b2[3] = {bz2, br2, bh2};
            const float* l2[3] = {lzw2, lrw2, lhw2};
            const float* p2[3] = {lzb2, lrb2, lhb2};
            for (int g = 0; g < 3; g++) {
                float c = 0.f;
                for (int q = 0; q < HIDD; q++) c += b2[g][q] * l2[g][q * HIDD + tid];
                g_c2[g * HIDD + tid] = c + p2[g][tid];
            }
        }
    } else {
        __shared__ float wrow[HIDD];
        int id = blockIdx.x - 1;
        int g = id >> 7, k = id & 127;
        const float* W = (g == 0) ? Wz2 : ((g == 1) ? Wr2 : Wh2);
        const float* L = (g == 0) ? lzw2 : ((g == 1) ? lrw2 : lhw2);
        if (tid < HIDD) wrow[tid] = W[k * HIDD + tid];
        __syncthreads();
        if (tid < HIDD) {
            float a = 0.f;
            for (int q = 0; q < HIDD; q++) a += wrow[q] * L[q * HIDD + tid];
            g_W2L[g * HIDD * HIDD + k * HIDD + tid] = a;
        }
    }
}

// ---------------- staging (prefetched one pass ahead) ----------------
template <int NM>
__device__ __forceinline__ void stage_chunk(float* buf, const float* G0, const float* G1,
                                            int c, int tid) {
    int e = tid * 8;
    int row = e >> 6, col = e & 63;
    long off = (long)(c * 32 + row) * HIDD + col;
    float* reg = buf + c * (NM * CHUNK_F);
    cpa16(reg + e, G0 + off);
    cpa16(reg + e + 4, G0 + off + 4);
    if (NM > 1) {
        cpa16(reg + CHUNK_F + e, G1 + off);
        cpa16(reg + CHUNK_F + e + 4, G1 + off + 4);
    }
}
template <int NM>
__device__ __forceinline__ void stage_pass(float* buf, const float* G0, const float* G1, int tid) {
#pragma unroll
    for (int c = 0; c < 4; c++) stage_chunk<NM>(buf, G0, G1, c, tid);
    cpcommit();
}

// ---------------- compute 32 k's from a staged chunk ----------------
template <int NM>
__device__ __forceinline__ void mm32(const float* __restrict__ S, int kbase,
                                     const float* __restrict__ B,
                                     int i0, int ui, u64 (&A)[NM][3][2]) {
#pragma unroll 2
    for (int k4 = 0; k4 < 8; k4++) {
        float sa[3][4];
#pragma unroll
        for (int r = 0; r < 3; r++) {
            float4 q = *reinterpret_cast<const float4*>(S + (i0 + r) * HSTR + kbase + k4 * 4);
            sa[r][0] = q.x; sa[r][1] = q.y; sa[r][2] = q.z; sa[r][3] = q.w;
        }
#pragma unroll
        for (int kk = 0; kk < 4; kk++) {
            int k = k4 * 4 + kk;
            ulonglong2 ua, ub;
            ua = *(reinterpret_cast<const ulonglong2*>(B) + k * 16 + ui);
            if (NM > 1) ub = *(reinterpret_cast<const ulonglong2*>(B + CHUNK_F) + k * 16 + ui);
#pragma unroll
            for (int r = 0; r < 3; r++) {
                u64 s = bc2(sa[r][kk]);
                A[0][r][0] = fma2(s, ua.x, A[0][r][0]);
                A[0][r][1] = fma2(s, ua.y, A[0][r][1]);
                if (NM > 1) {
                    A[1][r][0] = fma2(s, ub.x, A[1][r][0]);
                    A[1][r][1] = fma2(s, ub.y, A[1][r][1]);
                }
            }
        }
    }
}

// Full split-k pass with cross-pass weight prefetch. After return, EVERY thread
// holds the full k-sum in A[.][.][kh] (its 2-column epilogue half).
template <int NM, int NMn>
__device__ __forceinline__ void run_pass(const float* __restrict__ S,
                                         const float* __restrict__ bufC,
                                         float* bufN, const float* Gn0, const float* Gn1,
                                         u64* scx, int tid, int kh, int i0, int ui,
                                         u64 (&A)[NM][3][2]) {
    cpwait<0>();       // weights staged during previous pass -> instant
    __syncthreads();   // #1: staged data + prev epilogue S-writes visible; prev scratch reads done
    const int cA = kh * 2, cB = kh * 2 + 1;
    mm32<NM>(S, cA * 32, bufC + cA * (NM * CHUNK_F), i0, ui, A);
    mm32<NM>(S, cB * 32, bufC + cB * (NM * CHUNK_F), i0, ui, A);
    stage_pass<NMn>(bufN, Gn0, Gn1, tid);   // prefetch next pass's weights
    // symmetric k-half exchange: each half sends the COMPLEMENTARY column-half partials
    u64* my = scx + (size_t)kh * (128 * 7) + (tid & 127) * 7;
#pragma unroll
    for (int m = 0; m < NM; m++)
#pragma unroll
        for (int r = 0; r < 3; r++)
            my[m * 3 + r] = A[m][r][kh ^ 1];
    __syncthreads();   // #2: partials visible
    const u64* ot = scx + (size_t)(kh ^ 1) * (128 * 7) + (tid & 127) * 7;
#pragma unroll
    for (int m = 0; m < NM; m++)
#pragma unroll
        for (int r = 0; r < 3; r++)
            A[m][r][kh] = add2(A[m][r][kh], ot[m * 3 + r]);
}

// A-mix over node range [j0,j1): acc += A[i,j] * M[j, local cols] (M stride ZSTR)
template <int NM>
__device__ __forceinline__ void amixN(const float* __restrict__ sA,
                                      const float* __restrict__ M0,
                                      const float* __restrict__ M1,
                                      int j0, int j1, int i0, int ui, u64 (&A)[NM][3][2]) {
    const ulonglong2* Ma = reinterpret_cast<const ulonglong2*>(M0);
    const ulonglong2* Mb = reinterpret_cast<const ulonglong2*>(M1);
    for (int j = j0; j < j1; j++) {
        ulonglong2 ma = Ma[j * (ZSTR / 4) + ui];
        ulonglong2 mb;
        if (NM > 1) mb = Mb[j * (ZSTR / 4) + ui];
#pragma unroll
        for (int r = 0; r < 3; r++) {
            u64 a = bc2(sA[(i0 + r) * NNODE + j]);
            A[0][r][0] = fma2(a, ma.x, A[0][r][0]);
            A[0][r][1] = fma2(a, ma.y, A[0][r][1]);
            if (NM > 1) {
                A[1][r][0] = fma2(a, mb.x, A[1][r][0]);
                A[1][r][1] = fma2(a, mb.y, A[1][r][1]);
            }
        }
    }
}

// ---------------- smem layout (floats) ----------------
#define BIG (NPAD * HSTR)          // 3168
#define ZBIG (NPAD * ZSTR)         // 1632
#define OFF_H1 0
#define OFF_H2 (OFF_H1 + BIG)
#define OFF_HR (OFF_H2 + BIG)
#define OFF_Z  (OFF_HR + BIG)
#define OFF_MA (OFF_Z + ZBIG)
#define OFF_MB (OFF_MA + ZBIG)
#define OFF_MC (OFF_MB + ZBIG)
#define OFF_A  (OFF_MC + ZBIG)     // 504
#define OFF_Y  (OFF_A + 504)       // 32
#define OFF_V  (OFF_Y + 32)        // 1152
#define OFF_W0 (OFF_V + 1152)      // 16384 (NM=2 buffer)
#define OFF_W1 (OFF_W0 + 16384)    // 8192  (NM=1 buffer)
#define OFF_SC (OFF_W1 + 8192)     // 3584  (scratch: 2 x 128 x 7 u64)
#define SMEM_FLOATS (OFF_SC + 3584)

__global__ void __launch_bounds__(NTHR, 1) __cluster_dims__(2, 1, 1) tgcn_main(
    const float* __restrict__ x,
    const float* __restrict__ Uz1, const float* __restrict__ Ur1, const float* __restrict__ Uh1,
    const float* __restrict__ Uz2, const float* __restrict__ Ur2, const float* __restrict__ Uh2,
    const float* __restrict__ clsw, const float* __restrict__ clsb,
    float* __restrict__ out) {
    extern __shared__ float sm[];
    float* sH1 = sm + OFF_H1;     // full 128-col state (global feature index)
    float* sH2 = sm + OFF_H2;
    float* sHR = sm + OFF_HR;
    float* sZ  = sm + OFF_Z;      // half-width, local cols, stride ZSTR
    float* sMa = sm + OFF_MA;
    float* sMb = sm + OFF_MB;
    float* sMc = sm + OFF_MC;
    float* sA  = sm + OFF_A;
    float* sy  = sm + OFF_Y;      // [24] = peer partial scratch
    float* sv  = sm + OFF_V;
    float* sw0 = sm + OFF_W0;
    float* sw1 = sm + OFF_W1;
    u64*   scx = reinterpret_cast<u64*>(sm + OFF_SC);
    float* svz = sv,        *svr = sv + 128,  *svh = sv + 256;
    float* scz = sv + 384,  *scrb = sv + 512, *sch = sv + 640;
    float* sc2z = sv + 768, *sc2r = sv + 896, *sc2h = sv + 1024;

    const int tid = threadIdx.x;
    const u32 rank = ctarank(), peer = 1 - rank;
    const int b = blockIdx.x >> 1;
    const int w = tid >> 5, lane = tid & 31;
    const int kh = w >> 2;              // k-half: warps 0-3 k[0,64), warps 4-7 k[64,128)
    const int wc = w & 3;               // col-warp (16 local cols each)
    const int fg = lane & 3, rg = lane >> 2;
    const int ui = wc * 4 + fg;         // local 16B unit, [0,16)
    const int f0 = ui * 4;              // local col [0,64)
    const int fgl = rank * FHALF + f0;  // global feature col
    const int i0 = rg * 3;              // 3 rows (rows 21-23 padding at rg==7)
    const int coff = kh * 2;            // this thread's epilogue column offset (2 cols)

    for (int i = tid; i < BIG; i += NTHR) { sH1[i] = 0.f; sH2[i] = 0.f; }
    for (int i = tid; i < 504; i += NTHR) sA[i] = (i < NNODE * NNODE) ? g_A[i] : 0.f;
    if (tid < 32) sy[tid] = 0.f;
    if (tid < HIDD)
        for (int g = 0; g < 9; g++)
            sv[g * 128 + tid] = (g < 6) ? g_fold1[g * 128 + tid] : g_c2[(g - 6) * 128 + tid];
    __syncthreads();
    CLUSTER_ARRIVE();                    // gen 0: init done

    float accS[6];
#pragma unroll
    for (int q = 0; q < 6; q++) accS[q] = 0.f;

    const float* xb = x + (size_t)b * TSTEPS * NNODE;
    const float* W2Lz = g_W2L + rank * FHALF;
    const float* W2Lr = g_W2L + HIDD * HIDD + rank * FHALF;
    const float* W2Lh = g_W2L + 2 * HIDD * HIDD + rank * FHALF;
    const float* Vz1 = Uz1 + rank * FHALF;
    const float* Vr1 = Ur1 + rank * FHALF;
    const float* Vh1 = Uh1 + rank * FHALF;
    const float* Vz2 = Uz2 + rank * FHALF;
    const float* Vr2 = Ur2 + rank * FHALF;
    const float* Vh2 = Uh2 + rank * FHALF;

    stage_pass<2>(sw0, Vz1, Vr1, tid);   // prime pipeline: P1 weights

    for (int t = 0; t < TSTEPS; t++) {
        CLUSTER_WAIT();                  // peer finished prev step

        // y = A @ x_t (consumed after P1's internal barriers)
        if (tid < NNODE) {
            const float* xr = xb + t * NNODE;
            float a = 0.f;
#pragma unroll
            for (int j = 0; j < NNODE; j++) a += sA[tid * NNODE + j] * xr[j];
            sy[tid] = a;
        }

        // ---- P1: Z1, R1 (S = full H1); prefetch P2 (Vh1 -> sw1) ----
        {
            u64 A[2][3][2] = {};
            run_pass<2, 1>(sH1, sw0, sw1, Vh1, nullptr, scx, tid, kh, i0, ui, A);
#pragma unroll
            for (int r = 0; r < 3; r++) {
                int i = i0 + r; float yv = sy[i];
                int f = fgl + coff;
                float v0, v1, q0, q1;
                up2(A[0][r][kh], v0, v1);
                up2(A[1][r][kh], q0, q1);
                float2 h2 = *reinterpret_cast<const float2*>(sH1 + i * HSTR + f);
                float z0 = sigm(fmaf(yv, svz[f], scz[f]) + v0);
                float z1 = sigm(fmaf(yv, svz[f + 1], scz[f + 1]) + v1);
                float r0 = sigm(fmaf(yv, svr[f], scrb[f]) + q0) * h2.x;
                float r1 = sigm(fmaf(yv, svr[f + 1], scrb[f + 1]) + q1) * h2.y;
                *reinterpret_cast<float2*>(sZ + i * ZSTR + f0 + coff) = make_float2(z0, z1);
                *reinterpret_cast<float2*>(sHR + i * HSTR + f) = make_float2(r0, r1);
                st_peer_u64(smem_u32(sHR + i * HSTR + f), peer, pk2(r0, r1));
            }
        }
        CLUSTER_ARRIVE();   // HR exchanged
        CLUSTER_WAIT();

        // ---- P2: Ht1 + blend into H1 (S = full HR); prefetch P3 (W2Lz,W2Lr -> sw0) ----
        {
            u64 A[1][3][2] = {};
            run_pass<1, 2>(sHR, sw1, sw0, W2Lz, W2Lr, scx, tid, kh, i0, ui, A);
#pragma unroll
            for (int r = 0; r < 3; r++) {
                int i = i0 + r; float yv = sy[i];
                int f = fgl + coff;
                float v0, v1;
                up2(A[0][r][kh], v0, v1);
                float2 h2 = *reinterpret_cast<const float2*>(sH1 + i * HSTR + f);
                float2 z2 = *reinterpret_cast<const float2*>(sZ + i * ZSTR + f0 + coff);
                float hh0 = tanh_(fmaf(yv, svh[f], sch[f]) + v0);
                float hh1 = tanh_(fmaf(yv, svh[f + 1], sch[f + 1]) + v1);
                float n0 = fmaf(z2.x, h2.x - hh0, hh0);
                float n1 = fmaf(z2.y, h2.y - hh1, hh1);
                *reinterpret_cast<float2*>(sH1 + i * HSTR + f) = make_float2(n0, n1);
                st_peer_u64(smem_u32(sH1 + i * HSTR + f), peer, pk2(n0, n1));
            }
        }
        CLUSTER_ARRIVE();   // H1 exchanged
        CLUSTER_WAIT();

        // ---- P3: Mz, Mr = H1 @ W2L{z,r}; prefetch P4 (W2Lh -> sw1) ----
        {
            u64 A[2][3][2] = {};
            run_pass<2, 1>(sH1, sw0, sw1, W2Lh, nullptr, scx, tid, kh, i0, ui, A);
#pragma unroll
            for (int r = 0; r < 3; r++) {
                int i = i0 + r;
                float a0, a1, b0, b1;
                up2(A[0][r][kh], a0, a1);
                up2(A[1][r][kh], b0, b1);
                *reinterpret_cast<float2*>(sMa + i * ZSTR + f0 + coff) = make_float2(a0, a1);
                *reinterpret_cast<float2*>(sMb + i * ZSTR + f0 + coff) = make_float2(b0, b1);
            }
        }

        // ---- P4: Mh = H1 @ W2Lh; prefetch P5 (Vz2,Vr2 -> sw0) ----
        {
            u64 A[1][3][2] = {};
            run_pass<1, 2>(sH1, sw1, sw0, Vz2, Vr2, scx, tid, kh, i0, ui, A);
#pragma unroll
            for (int r = 0; r < 3; r++) {
                int i = i0 + r;
                float a0, a1;
                up2(A[0][r][kh], a0, a1);
                *reinterpret_cast<float2*>(sMc + i * ZSTR + f0 + coff) = make_float2(a0, a1);
            }
        }

        // ---- P5: Z2 / R2 (bias + split amix + H2 matmul); prefetch P6 (Vh2 -> sw1) ----
        {
            u64 A[2][3][2];
            if (kh == 0) {
                u64 cz0 = pk2(sc2z[fgl], sc2z[fgl + 1]), cz1 = pk2(sc2z[fgl + 2], sc2z[fgl + 3]);
                u64 cr0 = pk2(sc2r[fgl], sc2r[fgl + 1]), cr1 = pk2(sc2r[fgl + 2], sc2r[fgl + 3]);
#pragma unroll
                for (int r = 0; r < 3; r++) {
                    A[0][r][0] = cz0; A[0][r][1] = cz1;
                    A[1][r][0] = cr0; A[1][r][1] = cr1;
                }
                amixN<2>(sA, sMa, sMb, 0, 11, i0, ui, A);
            } else {
#pragma unroll
                for (int r = 0; r < 3; r++) {
                    A[0][r][0] = 0; A[0][r][1] = 0;
                    A[1][r][0] = 0; A[1][r][1] = 0;
                }
                amixN<2>(sA, sMa, sMb, 11, NNODE, i0, ui, A);
            }
            run_pass<2, 1>(sH2, sw0, sw1, Vh2, nullptr, scx, tid, kh, i0, ui, A);
#pragma unroll
            for (int r = 0; r < 3; r++) {
                int i = i0 + r;
                int f = fgl + coff;
                float v0, v1, q0, q1;
                up2(A[0][r][kh], v0, v1);
                up2(A[1][r][kh], q0, q1);
                float2 h2 = *reinterpret_cast<const float2*>(sH2 + i * HSTR + f);
                float z0 = sigm(v0), z1 = sigm(v1);
                float r0 = sigm(q0) * h2.x, r1 = sigm(q1) * h2.y;
                *reinterpret_cast<float2*>(sZ + i * ZSTR + f0 + coff) = make_float2(z0, z1);
                *reinterpret_cast<float2*>(sHR + i * HSTR + f) = make_float2(r0, r1);
                st_peer_u64(smem_u32(sHR + i * HSTR + f), peer, pk2(r0, r1));
            }
        }
        CLUSTER_ARRIVE();   // HR2 exchanged
        CLUSTER_WAIT();

        // ---- P6: Ht2 + blend into H2 + output acc; prefetch NEXT STEP P1 (Vz1,Vr1 -> sw0) ----
        {
            u64 A[1][3][2];
            if (kh == 0) {
                u64 ch0 = pk2(sc2h[fgl], sc2h[fgl + 1]), ch1 = pk2(sc2h[fgl + 2], sc2h[fgl + 3]);
#pragma unroll
                for (int r = 0; r < 3; r++) { A[0][r][0] = ch0; A[0][r][1] = ch1; }
                amixN<1>(sA, sMc, nullptr, 0, 11, i0, ui, A);
            } else {
#pragma unroll
                for (int r = 0; r < 3; r++) { A[0][r][0] = 0; A[0][r][1] = 0; }
                amixN<1>(sA, sMc, nullptr, 11, NNODE, i0, ui, A);
            }
            run_pass<1, 2>(sHR, sw1, sw0, Vz1, Vr1, scx, tid, kh, i0, ui, A);
#pragma unroll
            for (int r = 0; r < 3; r++) {
                int i = i0 + r;
                int f = fgl + coff;
                float v0, v1;
                up2(A[0][r][kh], v0, v1);
                float2 h2 = *reinterpret_cast<const float2*>(sH2 + i * HSTR + f);
                float2 z2 = *reinterpret_cast<const float2*>(sZ + i * ZSTR + f0 + coff);
                float hh0 = tanh_(v0), hh1 = tanh_(v1);
                float n0 = fmaf(z2.x, h2.x - hh0, hh0);
                float n1 = fmaf(z2.y, h2.y - hh1, hh1);
                if (rg < 7) { accS[r * 2] += n0; accS[r * 2 + 1] += n1; }
                *reinterpret_cast<float2*>(sH2 + i * HSTR + f) = make_float2(n0, n1);
                st_peer_u64(smem_u32(sH2 + i * HSTR + f), peer, pk2(n0, n1));
            }
        }
        CLUSTER_ARRIVE();   // H2 exchanged (consumed next step P5)
    }
    cpwait<0>();
    CLUSTER_WAIT();          // matches last arrive

    // ---- final: each thread holds 2-col sums; combine over rows, then cluster ----
    __syncthreads();
    if (rg < 7) {
        float c0 = accS[0] + accS[2] + accS[4];
        float c1 = accS[1] + accS[3] + accS[5];
        *reinterpret_cast<float2*>(sMa + rg * ZSTR + f0 + coff) = make_float2(c0, c1);
    }
    __syncthreads();
    if (tid < FHALF) {
        float s = 0.f;
#pragma unroll
        for (int r = 0; r < 7; r++) s += sMa[r * ZSTR + tid];
        s *= (1.0f / (float)(NNODE * TSTEPS));
        sMb[tid] = s * clsw[rank * FHALF + tid];
    }
    __syncthreads();
    float own = 0.f;
    if (tid == 0) {
        for (int f = 0; f < FHALF; f++) own += sMb[f];
        if (rank == 1) st_peer_u32(smem_u32(sy + 24), 0, __float_as_uint(own));
    }
    CLUSTER_ARRIVE();
    CLUSTER_WAIT();
    if (rank == 0 && tid == 0)
        out[b] = own + sy[24] + clsb[0];
}

// ---------------- launch ----------------
extern "C" void kernel_launch(void* const* d_in, const int* in_sizes, int n_in,
                              void* d_out, int out_size) {
    const float* x    = (const float*)d_in[0];
    const int*   ei   = (const int*)d_in[1];
    const float* ew   = (const float*)d_in[2];
    const float* Wz1  = (const float*)d_in[3];
    const float* bz1  = (const float*)d_in[4];
    const float* lzw1 = (const float*)d_in[5];
    const float* lzb1 = (const float*)d_in[6];
    const float* Wr1  = (const float*)d_in[7];
    const float* br1  = (const float*)d_in[8];
    const float* lrw1 = (const float*)d_in[9];
    const float* lrb1 = (const float*)d_in[10];
    const float* Wh1  = (const float*)d_in[11];
    const float* bh1  = (const float*)d_in[12];
    const float* lhw1 = (const float*)d_in[13];
    const float* lhb1 = (const float*)d_in[14];
    const float* Wz2  = (const float*)d_in[15];
    const float* bz2  = (const float*)d_in[16];
    const float* lzw2 = (const float*)d_in[17];
    const float* lzb2 = (const float*)d_in[18];
    const float* Wr2  = (const float*)d_in[19];
    const float* br2  = (const float*)d_in[20];
    const float* lrw2 = (const float*)d_in[21];
    const float* lrb2 = (const float*)d_in[22];
    const float* Wh2  = (const float*)d_in[23];
    const float* bh2  = (const float*)d_in[24];
    const float* lhw2 = (const float*)d_in[25];
    const float* lhb2 = (const float*)d_in[26];
    const float* clsw = (const float*)d_in[27];
    const float* clsb = (const float*)d_in[28];
    float* out = (float*)d_out;

    setup_all<<<385, 448>>>(ei, ew,
        Wz1, bz1, lzw1, lzb1, Wr1, br1, lrw1, lrb1, Wh1, bh1, lhw1, lhb1,
        Wz2, bz2, lzw2, lzb2, Wr2, br2, lrw2, lrb2, Wh2, bh2, lhw2, lhb2);

    const int smem_bytes = SMEM_FLOATS * (int)sizeof(float);  // ~183.5 KB
    cudaFuncSetAttribute(tgcn_main, cudaFuncAttributeMaxDynamicSharedMemorySize, smem_bytes);
    tgcn_main<<<128, NTHR, smem_bytes>>>(
        x,
        lzw1 + HIDD * HIDD, lrw1 + HIDD * HIDD, lhw1 + HIDD * HIDD,
        lzw2 + HIDD * HIDD, lrw2 + HIDD * HIDD, lhw2 + HIDD * HIDD,
        clsw, clsb, out);
}

// round 12
// speedup vs baseline: 1.1835x; 1.1835x over previous
#include <cuda_runtime.h>
#include <cstdint>

#define NNODE 21
#define NPAD 24
#define HIDD 128
#define HSTR 132            // padded smem row stride (floats): conflict-free row broadcasts
#define TSTEPS 500
#define NEDGE 210
#define NTHR 256
#define FHALF 64            // features per CTA (cluster of 2)
#define CHUNK_F 2048        // floats per 32-k x 64-col weight chunk

typedef unsigned long long u64;
typedef unsigned int u32;

// ---------------- packed f32x2 helpers ----------------
__device__ __forceinline__ u64 pk2(float lo, float hi) {
    u64 r; asm("mov.b64 %0,{%1,%2};" : "=l"(r) : "f"(lo), "f"(hi)); return r;
}
__device__ __forceinline__ u64 bc2(float v) {
    u64 r; asm("mov.b64 %0,{%1,%1};" : "=l"(r) : "f"(v)); return r;
}
__device__ __forceinline__ u64 fma2(u64 a, u64 b, u64 c) {
    u64 d; asm("fma.rn.f32x2 %0,%1,%2,%3;" : "=l"(d) : "l"(a), "l"(b), "l"(c)); return d;
}
__device__ __forceinline__ u64 add2(u64 a, u64 b) {
    u64 d; asm("add.rn.f32x2 %0,%1,%2;" : "=l"(d) : "l"(a), "l"(b)); return d;
}
__device__ __forceinline__ void up2(u64 v, float& lo, float& hi) {
    asm("mov.b64 {%0,%1},%2;" : "=f"(lo), "=f"(hi) : "l"(v));
}
__device__ __forceinline__ float sigm(float v) {
    return __fdividef(1.0f, 1.0f + __expf(-v));
}
__device__ __forceinline__ float tanh_(float v) {
    return 1.0f - __fdividef(2.0f, __expf(2.0f * v) + 1.0f);
}

// ---------------- cp.async helpers ----------------
__device__ __forceinline__ void cpa16(void* dst, const void* src) {
    u32 d = (u32)__cvta_generic_to_shared(dst);
    asm volatile("cp.async.cg.shared.global [%0], [%1], 16;\n" :: "r"(d), "l"(src));
}
__device__ __forceinline__ void cpcommit() { asm volatile("cp.async.commit_group;\n"); }
template <int N> __device__ __forceinline__ void cpwait() {
    asm volatile("cp.async.wait_group %0;\n" :: "n"(N));
}

// ---------------- cluster helpers ----------------
#define CLUSTER_ARRIVE() asm volatile("barrier.cluster.arrive.aligned;" ::: "memory")
#define CLUSTER_WAIT()   asm volatile("barrier.cluster.wait.aligned;" ::: "memory")

__device__ __forceinline__ u32 ctarank() {
    u32 r; asm("mov.u32 %0, %%cluster_ctarank;" : "=r"(r)); return r;
}
__device__ __forceinline__ void st_peer_u64(u32 laddr, u32 peer, u64 v) {
    u32 raddr;
    asm("mapa.shared::cluster.u32 %0, %1, %2;" : "=r"(raddr) : "r"(laddr), "r"(peer));
    asm volatile("st.shared::cluster.b64 [%0], %1;" :: "r"(raddr), "l"(v) : "memory");
}
__device__ __forceinline__ void st_peer_u32(u32 laddr, u32 peer, u32 v) {
    u32 raddr;
    asm("mapa.shared::cluster.u32 %0, %1, %2;" : "=r"(raddr) : "r"(laddr), "r"(peer));
    asm volatile("st.shared::cluster.b32 [%0], %1;" :: "r"(raddr), "r"(v) : "memory");
}
__device__ __forceinline__ u32 smem_u32(const void* p) {
    return (u32)__cvta_generic_to_shared(p);
}

// ---------------- device-global precomputed state ----------------
__device__ float g_A[NNODE * NNODE];
__device__ float g_fold1[6 * HIDD];
__device__ float g_c2[3 * HIDD];
__device__ __align__(16) float g_W2L[3 * HIDD * HIDD];

// ---------------- fused setup kernel ----------------
__global__ void setup_all(
    const int* __restrict__ ei, const float* __restrict__ ew,
    const float* Wz1, const float* bz1, const float* lzw1, const float* lzb1,
    const float* Wr1, const float* br1, const float* lrw1, const float* lrb1,
    const float* Wh1, const float* bh1, const float* lhw1, const float* lhb1,
    const float* Wz2, const float* bz2, const float* lzw2, const float* lzb2,
    const float* Wr2, const float* br2, const float* lrw2, const float* lrb2,
    const float* Wh2, const float* bh2, const float* lhw2, const float* lhb2) {
    int tid = threadIdx.x;
    if (blockIdx.x == 0) {
        __shared__ float dinv[NNODE];
        if (tid < NNODE) {
            float d = 1.0f;
            for (int e = 0; e < NEDGE; e++)
                if (ei[NEDGE + e] == tid) d += ew[e];
            dinv[tid] = (d > 0.f) ? (1.0f / sqrtf(d)) : 0.0f;
        }
        __syncthreads();
        if (tid < NNODE * NNODE) {
            int i = tid / NNODE, j = tid % NNODE;
            float a = (i == j) ? dinv[i] * dinv[i] : 0.0f;
            for (int e = 0; e < NEDGE; e++)
                if (ei[e] == j && ei[NEDGE + e] == i)
                    a += dinv[j] * ew[e] * dinv[i];
            g_A[tid] = a;
        }
        if (tid < HIDD) {
            const float* Ws[3] = {Wz1, Wr1, Wh1};
            const float* bs[3] = {bz1, br1, bh1};
            const float* ls[3] = {lzw1, lrw1, lhw1};
            const float* lb[3] = {lzb1, lrb1, lhb1};
            for (int g = 0; g < 3; g++) {
                float v = 0.f, c = 0.f;
                for (int q = 0; q < HIDD; q++) {
                    float l = ls[g][q * HIDD + tid];
                    v += Ws[g][q] * l;
                    c += bs[g][q] * l;
                }
                g_fold1[g * HIDD + tid] = v;
                g_fold1[(3 + g) * HIDD + tid] = c + lb[g][tid];
            }
            const float* b2[3] = {bz2, br2, bh2};
            const float* l2[3] = {lzw2, lrw2, lhw2};
            const float* p2[3] = {lzb2, lrb2, lhb2};
            for (int g = 0; g < 3; g++) {
                float c = 0.f;
                for (int q = 0; q < HIDD; q++) c += b2[g][q] * l2[g][q * HIDD + tid];
                g_c2[g * HIDD + tid] = c + p2[g][tid];
            }
        }
    } else {
        __shared__ float wrow[HIDD];
        int id = blockIdx.x - 1;
        int g = id >> 7, k = id & 127;
        const float* W = (g == 0) ? Wz2 : ((g == 1) ? Wr2 : Wh2);
        const float* L = (g == 0) ? lzw2 : ((g == 1) ? lrw2 : lhw2);
        if (tid < HIDD) wrow[tid] = W[k * HIDD + tid];
        __syncthreads();
        if (tid < HIDD) {
            float a = 0.f;
            for (int q = 0; q < HIDD; q++) a += wrow[q] * L[q * HIDD + tid];
            g_W2L[g * HIDD * HIDD + k * HIDD + tid] = a;
        }
    }
}

// ---------------- staging (prefetched one pass ahead) ----------------
template <int NM>
__device__ __forceinline__ void stage_chunk(float* buf, const float* G0, const float* G1,
                                            int c, int tid) {
    int e = tid * 8;
    int row = e >> 6, col = e & 63;
    long off = (long)(c * 32 + row) * HIDD + col;
    float* reg = buf + c * (NM * CHUNK_F);
    cpa16(reg + e, G0 + off);
    cpa16(reg + e + 4, G0 + off + 4);
    if (NM > 1) {
        cpa16(reg + CHUNK_F + e, G1 + off);
        cpa16(reg + CHUNK_F + e + 4, G1 + off + 4);
    }
}
template <int NM>
__device__ __forceinline__ void stage_pass(float* buf, const float* G0, const float* G1, int tid) {
#pragma unroll
    for (int c = 0; c < 4; c++) stage_chunk<NM>(buf, G0, G1, c, tid);
    cpcommit();
}

// ---------------- compute 32 k's from a staged chunk ----------------
template <int NM>
__device__ __forceinline__ void mm32(const float* __restrict__ S, int kbase,
                                     const float* __restrict__ B,
                                     int i0, int ui, u64 (&A)[NM][3][2]) {
#pragma unroll 2
    for (int k4 = 0; k4 < 8; k4++) {
        float sa[3][4];
#pragma unroll
        for (int r = 0; r < 3; r++) {
            float4 q = *reinterpret_cast<const float4*>(S + (i0 + r) * HSTR + kbase + k4 * 4);
            sa[r][0] = q.x; sa[r][1] = q.y; sa[r][2] = q.z; sa[r][3] = q.w;
        }
#pragma unroll
        for (int kk = 0; kk < 4; kk++) {
            int k = k4 * 4 + kk;
            ulonglong2 ua, ub;
            ua = *(reinterpret_cast<const ulonglong2*>(B) + k * 16 + ui);
            if (NM > 1) ub = *(reinterpret_cast<const ulonglong2*>(B + CHUNK_F) + k * 16 + ui);
#pragma unroll
            for (int r = 0; r < 3; r++) {
                u64 s = bc2(sa[r][kk]);
                A[0][r][0] = fma2(s, ua.x, A[0][r][0]);
                A[0][r][1] = fma2(s, ua.y, A[0][r][1]);
                if (NM > 1) {
                    A[1][r][0] = fma2(s, ub.x, A[1][r][0]);
                    A[1][r][1] = fma2(s, ub.y, A[1][r][1]);
                }
            }
        }
    }
}

// Full split-k pass, weights prefetched one pass ahead into bufC.
// Prefetches NEXT pass's weights into bufN during this pass's compute.
// R9-style asymmetric combine: after return, kh0 lanes (tid<128) hold the full k-sum.
template <int NM, int NMn>
__device__ __forceinline__ void run_pass(const float* __restrict__ S,
                                         const float* __restrict__ bufC,
                                         float* bufN, const float* Gn0, const float* Gn1,
                                         u64* scx, int tid, int kh, int i0, int ui,
                                         u64 (&A)[NM][3][2]) {
    cpwait<0>();       // this pass's weights were staged during the previous pass
    __syncthreads();   // #1: staged data + prev epilogue S-writes visible; prev scratch reads done
    const int cA = kh * 2, cB = kh * 2 + 1;
    mm32<NM>(S, cA * 32, bufC + cA * (NM * CHUNK_F), i0, ui, A);
    mm32<NM>(S, cB * 32, bufC + cB * (NM * CHUNK_F), i0, ui, A);
    stage_pass<NMn>(bufN, Gn0, Gn1, tid);   // prefetch next pass's weights
    // k-reduction: kh1 sends full partials to dedicated scratch, kh0 combines
    const int SSTR = NM * 6 + 1;   // u64 stride, odd -> low bank conflict
    if (kh == 1) {
        u64* scr = scx + (tid - 128) * SSTR;
#pragma unroll
        for (int m = 0; m < NM; m++)
#pragma unroll
            for (int r = 0; r < 3; r++) {
                scr[m * 6 + r * 2] = A[m][r][0];
                scr[m * 6 + r * 2 + 1] = A[m][r][1];
            }
    }
    __syncthreads();   // #2: partials visible
    if (kh == 0) {
        const u64* scr = scx + tid * SSTR;
#pragma unroll
        for (int m = 0; m < NM; m++)
#pragma unroll
            for (int r = 0; r < 3; r++) {
                A[m][r][0] = add2(A[m][r][0], scr[m * 6 + r * 2]);
                A[m][r][1] = add2(A[m][r][1], scr[m * 6 + r * 2 + 1]);
            }
    }
}

// A-mix over node range [j0,j1): acc += A[i,j] * M[j, local cols] (M stride HSTR)
template <int NM>
__device__ __forceinline__ void amixN(const float* __restrict__ sA,
                                      const float* __restrict__ M0,
                                      const float* __restrict__ M1,
                                      int j0, int j1, int i0, int ui, u64 (&A)[NM][3][2]) {
    const ulonglong2* Ma = reinterpret_cast<const ulonglong2*>(M0);
    const ulonglong2* Mb = reinterpret_cast<const ulonglong2*>(M1);
    for (int j = j0; j < j1; j++) {
        ulonglong2 ma = Ma[j * (HSTR / 4) + ui];
        ulonglong2 mb;
        if (NM > 1) mb = Mb[j * (HSTR / 4) + ui];
#pragma unroll
        for (int r = 0; r < 3; r++) {
            u64 a = bc2(sA[(i0 + r) * NNODE + j]);
            A[0][r][0] = fma2(a, ma.x, A[0][r][0]);
            A[0][r][1] = fma2(a, ma.y, A[0][r][1]);
            if (NM > 1) {
                A[1][r][0] = fma2(a, mb.x, A[1][r][0]);
                A[1][r][1] = fma2(a, mb.y, A[1][r][1]);
            }
        }
    }
}

// ---------------- smem layout (floats) ----------------
#define BIG (NPAD * HSTR)            // 3168 floats per state array
#define OFF_H1 0
#define OFF_H2 (OFF_H1 + BIG)
#define OFF_HR (OFF_H2 + BIG)
#define OFF_Z  (OFF_HR + BIG)
#define OFF_MA (OFF_Z + BIG)
#define OFF_MB (OFF_MA + BIG)
#define OFF_MC (OFF_MB + BIG)
#define OFF_A  (OFF_MC + BIG)        // 504 (24x21)
#define OFF_Y  (OFF_A + 504)         // 32 ([24] = peer partial scratch)
#define OFF_V  (OFF_Y + 32)          // 1152
#define OFF_W0 (OFF_V + 1152)        // 16384 (NM=2 buffer: P1,P3,P5)
#define OFF_W1 (OFF_W0 + 16384)      // 8192  (NM=1 buffer: P2,P4,P6)
#define OFF_SC (OFF_W1 + 8192)       // 3328  (dedicated scratch: 128 x 13 u64)
#define SMEM_FLOATS (OFF_SC + 3328)  // 51768 floats = 207072 B

__global__ void __launch_bounds__(NTHR, 1) __cluster_dims__(2, 1, 1) tgcn_main(
    const float* __restrict__ x,
    const float* __restrict__ Uz1, const float* __restrict__ Ur1, const float* __restrict__ Uh1,
    const float* __restrict__ Uz2, const float* __restrict__ Ur2, const float* __restrict__ Uh2,
    const float* __restrict__ clsw, const float* __restrict__ clsb,
    float* __restrict__ out) {
    extern __shared__ float sm[];
    float* sH1 = sm + OFF_H1;     // full 128-col state (global feature index)
    float* sH2 = sm + OFF_H2;
    float* sHR = sm + OFF_HR;
    float* sZ  = sm + OFF_Z;      // own half used (global index)
    float* sMa = sm + OFF_MA;     // own half (local cols 0..63)
    float* sMb = sm + OFF_MB;
    float* sMc = sm + OFF_MC;
    float* sA  = sm + OFF_A;
    float* sy  = sm + OFF_Y;
    float* sv  = sm + OFF_V;
    float* sw0 = sm + OFF_W0;
    float* sw1 = sm + OFF_W1;
    u64*   scx = reinterpret_cast<u64*>(sm + OFF_SC);
    float* svz = sv,        *svr = sv + 128,  *svh = sv + 256;
    float* scz = sv + 384,  *scrb = sv + 512, *sch = sv + 640;
    float* sc2z = sv + 768, *sc2r = sv + 896, *sc2h = sv + 1024;

    const int tid = threadIdx.x;
    const u32 rank = ctarank(), peer = 1 - rank;
    const int b = blockIdx.x >> 1;
    const int w = tid >> 5, lane = tid & 31;
    const int kh = w >> 2;              // k-half: warps 0-3 k[0,64), warps 4-7 k[64,128)
    const int wc = w & 3;               // col-warp (16 local cols each)
    const int fg = lane & 3, rg = lane >> 2;
    const int ui = wc * 4 + fg;         // local 16B unit, [0,16)
    const int f0 = ui * 4;              // local col [0,64)
    const int fgl = rank * FHALF + f0;  // global feature col
    const int i0 = rg * 3;              // 3 rows (rows 21-23 padding at rg==7)

    for (int i = tid; i < BIG; i += NTHR) { sH1[i] = 0.f; sH2[i] = 0.f; }
    for (int i = tid; i < 504; i += NTHR) sA[i] = (i < NNODE * NNODE) ? g_A[i] : 0.f;
    if (tid < 32) sy[tid] = 0.f;
    if (tid < HIDD)
        for (int g = 0; g < 9; g++)
            sv[g * 128 + tid] = (g < 6) ? g_fold1[g * 128 + tid] : g_c2[(g - 6) * 128 + tid];
    __syncthreads();
    CLUSTER_ARRIVE();                    // gen 0: init done

    float accS[12];
#pragma unroll
    for (int q = 0; q < 12; q++) accS[q] = 0.f;

    const float* xb = x + (size_t)b * TSTEPS * NNODE;
    const float* W2Lz = g_W2L + rank * FHALF;
    const float* W2Lr = g_W2L + HIDD * HIDD + rank * FHALF;
    const float* W2Lh = g_W2L + 2 * HIDD * HIDD + rank * FHALF;
    const float* Vz1 = Uz1 + rank * FHALF;
    const float* Vr1 = Ur1 + rank * FHALF;
    const float* Vh1 = Uh1 + rank * FHALF;
    const float* Vz2 = Uz2 + rank * FHALF;
    const float* Vr2 = Ur2 + rank * FHALF;
    const float* Vh2 = Uh2 + rank * FHALF;

    stage_pass<2>(sw0, Vz1, Vr1, tid);   // prime: P1 weights

    for (int t = 0; t < TSTEPS; t++) {
        CLUSTER_WAIT();                  // peer finished prev step

        // y = A @ x_t (consumed after P1's internal barriers)
        if (tid < NNODE) {
            const float* xr = xb + t * NNODE;
            float a = 0.f;
#pragma unroll
            for (int j = 0; j < NNODE; j++) a += sA[tid * NNODE + j] * xr[j];
            sy[tid] = a;
        }

        // ---- P1: Z1, R1 (S = full H1); prefetch P2 (Vh1 -> sw1) ----
        {
            u64 A[2][3][2] = {};
            run_pass<2, 1>(sH1, sw0, sw1, Vh1, nullptr, scx, tid, kh, i0, ui, A);
            if (tid < 128) {
#pragma unroll
                for (int r = 0; r < 3; r++) {
                    int i = i0 + r; float yv = sy[i];
                    float v[4], q[4];
                    up2(A[0][r][0], v[0], v[1]); up2(A[0][r][1], v[2], v[3]);
                    up2(A[1][r][0], q[0], q[1]); up2(A[1][r][1], q[2], q[3]);
                    float4 h4 = *reinterpret_cast<const float4*>(sH1 + i * HSTR + fgl);
                    float h[4] = {h4.x, h4.y, h4.z, h4.w};
                    float zz[4], rr[4];
#pragma unroll
                    for (int c = 0; c < 4; c++) {
                        int f = fgl + c;
                        zz[c] = sigm(fmaf(yv, svz[f], scz[f]) + v[c]);
                        rr[c] = sigm(fmaf(yv, svr[f], scrb[f]) + q[c]) * h[c];
                    }
                    *reinterpret_cast<float4*>(sZ + i * HSTR + fgl) = make_float4(zz[0], zz[1], zz[2], zz[3]);
                    *reinterpret_cast<float4*>(sHR + i * HSTR + fgl) = make_float4(rr[0], rr[1], rr[2], rr[3]);
                    u32 la = smem_u32(sHR + i * HSTR + fgl);
                    st_peer_u64(la, peer, pk2(rr[0], rr[1]));
                    st_peer_u64(la + 8, peer, pk2(rr[2], rr[3]));
                }
            }
        }
        CLUSTER_ARRIVE();   // HR exchanged
        CLUSTER_WAIT();

        // ---- P2: Ht1 + blend into H1 (S = full HR); prefetch P3 (W2Lz,W2Lr -> sw0) ----
        {
            u64 A[1][3][2] = {};
            run_pass<1, 2>(sHR, sw1, sw0, W2Lz, W2Lr, scx, tid, kh, i0, ui, A);
            if (tid < 128) {
#pragma unroll
                for (int r = 0; r < 3; r++) {
                    int i = i0 + r; float yv = sy[i];
                    float v[4];
                    up2(A[0][r][0], v[0], v[1]); up2(A[0][r][1], v[2], v[3]);
                    float4 h4 = *reinterpret_cast<const float4*>(sH1 + i * HSTR + fgl);
                    float4 z4 = *reinterpret_cast<const float4*>(sZ + i * HSTR + fgl);
                    float h[4] = {h4.x, h4.y, h4.z, h4.w};
                    float z[4] = {z4.x, z4.y, z4.z, z4.w};
                    float nh[4];
#pragma unroll
                    for (int c = 0; c < 4; c++) {
                        int f = fgl + c;
                        float hh = tanh_(fmaf(yv, svh[f], sch[f]) + v[c]);
                        nh[c] = fmaf(z[c], h[c] - hh, hh);
                    }
                    *reinterpret_cast<float4*>(sH1 + i * HSTR + fgl) = make_float4(nh[0], nh[1], nh[2], nh[3]);
                    u32 la = smem_u32(sH1 + i * HSTR + fgl);
                    st_peer_u64(la, peer, pk2(nh[0], nh[1]));
                    st_peer_u64(la + 8, peer, pk2(nh[2], nh[3]));
                }
            }
        }
        CLUSTER_ARRIVE();   // H1 exchanged
        CLUSTER_WAIT();

        // ---- P3: Mz, Mr = H1 @ W2L{z,r}; prefetch P4 (W2Lh -> sw1) ----
        {
            u64 A[2][3][2] = {};
            run_pass<2, 1>(sH1, sw0, sw1, W2Lh, nullptr, scx, tid, kh, i0, ui, A);
            if (tid < 128) {
#pragma unroll
                for (int r = 0; r < 3; r++) {
                    int i = i0 + r;
                    float a[4], bq[4];
                    up2(A[0][r][0], a[0], a[1]); up2(A[0][r][1], a[2], a[3]);
                    up2(A[1][r][0], bq[0], bq[1]); up2(A[1][r][1], bq[2], bq[3]);
                    *reinterpret_cast<float4*>(sMa + i * HSTR + f0) = make_float4(a[0], a[1], a[2], a[3]);
                    *reinterpret_cast<float4*>(sMb + i * HSTR + f0) = make_float4(bq[0], bq[1], bq[2], bq[3]);
                }
            }
        }

        // ---- P4: Mh = H1 @ W2Lh; prefetch P5 (Vz2,Vr2 -> sw0) ----
        {
            u64 A[1][3][2] = {};
            run_pass<1, 2>(sH1, sw1, sw0, Vz2, Vr2, scx, tid, kh, i0, ui, A);
            if (tid < 128) {
#pragma unroll
                for (int r = 0; r < 3; r++) {
                    int i = i0 + r;
                    float a[4];
                    up2(A[0][r][0], a[0], a[1]); up2(A[0][r][1], a[2], a[3]);
                    *reinterpret_cast<float4*>(sMc + i * HSTR + f0) = make_float4(a[0], a[1], a[2], a[3]);
                }
            }
        }

        // ---- P5: Z2 / R2 (bias + split amix + H2 matmul); prefetch P6 (Vh2 -> sw1) ----
        {
            u64 A[2][3][2];
            if (kh == 0) {
                u64 cz0 = pk2(sc2z[fgl], sc2z[fgl + 1]), cz1 = pk2(sc2z[fgl + 2], sc2z[fgl + 3]);
                u64 cr0 = pk2(sc2r[fgl], sc2r[fgl + 1]), cr1 = pk2(sc2r[fgl + 2], sc2r[fgl + 3]);
#pragma unroll
                for (int r = 0; r < 3; r++) {
                    A[0][r][0] = cz0; A[0][r][1] = cz1;
                    A[1][r][0] = cr0; A[1][r][1] = cr1;
                }
                amixN<2>(sA, sMa, sMb, 0, 11, i0, ui, A);
            } else {
#pragma unroll
                for (int r = 0; r < 3; r++) {
                    A[0][r][0] = 0; A[0][r][1] = 0;
                    A[1][r][0] = 0; A[1][r][1] = 0;
                }
                amixN<2>(sA, sMa, sMb, 11, NNODE, i0, ui, A);
            }
            run_pass<2, 1>(sH2, sw0, sw1, Vh2, nullptr, scx, tid, kh, i0, ui, A);
            if (tid < 128) {
#pragma unroll
                for (int r = 0; r < 3; r++) {
                    int i = i0 + r;
                    float v[4], q[4];
                    up2(A[0][r][0], v[0], v[1]); up2(A[0][r][1], v[2], v[3]);
                    up2(A[1][r][0], q[0], q[1]); up2(A[1][r][1], q[2], q[3]);
                    float4 h4 = *reinterpret_cast<const float4*>(sH2 + i * HSTR + fgl);
                    float h[4] = {h4.x, h4.y, h4.z, h4.w};
                    float zz[4], rr[4];
#pragma unroll
                    for (int c = 0; c < 4; c++) {
                        zz[c] = sigm(v[c]);
                        rr[c] = sigm(q[c]) * h[c];
                    }
                    *reinterpret_cast<float4*>(sZ + i * HSTR + fgl) = make_float4(zz[0], zz[1], zz[2], zz[3]);
                    *reinterpret_cast<float4*>(sHR + i * HSTR + fgl) = make_float4(rr[0], rr[1], rr[2], rr[3]);
                    u32 la = smem_u32(sHR + i * HSTR + fgl);
                    st_peer_u64(la, peer, pk2(rr[0], rr[1]));
                    st_peer_u64(la + 8, peer, pk2(rr[2], rr[3]));
                }
            }
        }
        CLUSTER_ARRIVE();   // HR2 exchanged
        CLUSTER_WAIT();

        // ---- P6: Ht2 + blend into H2 + output acc; prefetch NEXT STEP P1 (Vz1,Vr1 -> sw0) ----
        {
            u64 A[1][3][2];
            if (kh == 0) {
                u64 ch0 = pk2(sc2h[fgl], sc2h[fgl + 1]), ch1 = pk2(sc2h[fgl + 2], sc2h[fgl + 3]);
#pragma unroll
                for (int r = 0; r < 3; r++) { A[0][r][0] = ch0; A[0][r][1] = ch1; }
                amixN<1>(sA, sMc, nullptr, 0, 11, i0, ui, A);
            } else {
#pragma unroll
                for (int r = 0; r < 3; r++) { A[0][r][0] = 0; A[0][r][1] = 0; }
                amixN<1>(sA, sMc, nullptr, 11, NNODE, i0, ui, A);
            }
            run_pass<1, 2>(sHR, sw1, sw0, Vz1, Vr1, scx, tid, kh, i0, ui, A);
            if (tid < 128) {
#pragma unroll
                for (int r = 0; r < 3; r++) {
                    int i = i0 + r;
                    float v[4];
                    up2(A[0][r][0], v[0], v[1]); up2(A[0][r][1], v[2], v[3]);
                    float4 h4 = *reinterpret_cast<const float4*>(sH2 + i * HSTR + fgl);
                    float4 z4 = *reinterpret_cast<const float4*>(sZ + i * HSTR + fgl);
                    float h[4] = {h4.x, h4.y, h4.z, h4.w};
                    float z[4] = {z4.x, z4.y, z4.z, z4.w};
                    float nh[4];
#pragma unroll
                    for (int c = 0; c < 4; c++) {
                        float hh = tanh_(v[c]);
                        nh[c] = fmaf(z[c], h[c] - hh, hh);
                        if (rg < 7) accS[r * 4 + c] += nh[c];
                    }
                    *reinterpret_cast<float4*>(sH2 + i * HSTR + fgl) = make_float4(nh[0], nh[1], nh[2], nh[3]);
                    u32 la = smem_u32(sH2 + i * HSTR + fgl);
                    st_peer_u64(la, peer, pk2(nh[0], nh[1]));
                    st_peer_u64(la + 8, peer, pk2(nh[2], nh[3]));
                }
            }
        }
        CLUSTER_ARRIVE();   // H2 exchanged (consumed next step P5)
    }
    cpwait<0>();
    CLUSTER_WAIT();          // matches last arrive

    // ---- final: partial over own 64 features; combine across cluster ----
    __syncthreads();
    if (tid < 128 && rg < 7) {
        float cs[4];
#pragma unroll
        for (int c = 0; c < 4; c++) cs[c] = accS[c] + accS[4 + c] + accS[8 + c];
        *reinterpret_cast<float4*>(sMa + rg * FHALF + f0) = make_float4(cs[0], cs[1], cs[2], cs[3]);
    }
    __syncthreads();
    if (tid < FHALF) {
        float s = 0.f;
#pragma unroll
        for (int r = 0; r < 7; r++) s += sMa[r * FHALF + tid];
        s *= (1.0f / (float)(NNODE * TSTEPS));
        sMb[tid] = s * clsw[rank * FHALF + tid];
    }
    __syncthreads();
    float own = 0.f;
    if (tid == 0) {
        for (int f = 0; f < FHALF; f++) own += sMb[f];
        if (rank == 1) st_peer_u32(smem_u32(sy + 24), 0, __float_as_uint(own));
    }
    CLUSTER_ARRIVE();
    CLUSTER_WAIT();
    if (rank == 0 && tid == 0)
        out[b] = own + sy[24] + clsb[0];
}

// ---------------- launch ----------------
extern "C" void kernel_launch(void* const* d_in, const int* in_sizes, int n_in,
                              void* d_out, int out_size) {
    const float* x    = (const float*)d_in[0];
    const int*   ei   = (const int*)d_in[1];
    const float* ew   = (const float*)d_in[2];
    const float* Wz1  = (const float*)d_in[3];
    const float* bz1  = (const float*)d_in[4];
    const float* lzw1 = (const float*)d_in[5];
    const float* lzb1 = (const float*)d_in[6];
    const float* Wr1  = (const float*)d_in[7];
    const float* br1  = (const float*)d_in[8];
    const float* lrw1 = (const float*)d_in[9];
    const float* lrb1 = (const float*)d_in[10];
    const float* Wh1  = (const float*)d_in[11];
    const float* bh1  = (const float*)d_in[12];
    const float* lhw1 = (const float*)d_in[13];
    const float* lhb1 = (const float*)d_in[14];
    const float* Wz2  = (const float*)d_in[15];
    const float* bz2  = (const float*)d_in[16];
    const float* lzw2 = (const float*)d_in[17];
    const float* lzb2 = (const float*)d_in[18];
    const float* Wr2  = (const float*)d_in[19];
    const float* br2  = (const float*)d_in[20];
    const float* lrw2 = (const float*)d_in[21];
    const float* lrb2 = (const float*)d_in[22];
    const float* Wh2  = (const float*)d_in[23];
    const float* bh2  = (const float*)d_in[24];
    const float* lhw2 = (const float*)d_in[25];
    const float* lhb2 = (const float*)d_in[26];
    const float* clsw = (const float*)d_in[27];
    const float* clsb = (const float*)d_in[28];
    float* out = (float*)d_out;

    setup_all<<<385, 448>>>(ei, ew,
        Wz1, bz1, lzw1, lzb1, Wr1, br1, lrw1, lrb1, Wh1, bh1, lhw1, lhb1,
        Wz2, bz2, lzw2, lzb2, Wr2, br2, lrw2, lrb2, Wh2, bh2, lhw2, lhb2);

    const int smem_bytes = SMEM_FLOATS * (int)sizeof(float);  // 207072
    cudaFuncSetAttribute(tgcn_main, cudaFuncAttributeMaxDynamicSharedMemorySize, smem_bytes);
    tgcn_main<<<128, NTHR, smem_bytes>>>(
        x,
        lzw1 + HIDD * HIDD, lrw1 + HIDD * HIDD, lhw1 + HIDD * HIDD,
        lzw2 + HIDD * HIDD, lrw2 + HIDD * HIDD, lhw2 + HIDD * HIDD,
        clsw, clsb, out);
}

// round 13
// speedup vs baseline: 1.2658x; 1.0695x over previous
#include <cuda_runtime.h>
#include <cstdint>

#define NNODE 21
#define NPAD 24
#define HIDD 128
#define HSTR 132            // full-width state row stride (floats), conflict-free
#define ZSTR 68             // half-width array row stride (floats)
#define TSTEPS 500
#define NEDGE 210
#define NTHR 512
#define FHALF 64            // features per CTA (cluster of 2)
#define CHUNK_F 2048        // floats per 32-k x 64-col weight chunk
#define SCREG 1664          // u64 per scratch region (128 x 13)

typedef unsigned long long u64;
typedef unsigned int u32;

// ---------------- packed f32x2 helpers ----------------
__device__ __forceinline__ u64 pk2(float lo, float hi) {
    u64 r; asm("mov.b64 %0,{%1,%2};" : "=l"(r) : "f"(lo), "f"(hi)); return r;
}
__device__ __forceinline__ u64 bc2(float v) {
    u64 r; asm("mov.b64 %0,{%1,%1};" : "=l"(r) : "f"(v)); return r;
}
__device__ __forceinline__ u64 fma2(u64 a, u64 b, u64 c) {
    u64 d; asm("fma.rn.f32x2 %0,%1,%2,%3;" : "=l"(d) : "l"(a), "l"(b), "l"(c)); return d;
}
__device__ __forceinline__ u64 add2(u64 a, u64 b) {
    u64 d; asm("add.rn.f32x2 %0,%1,%2;" : "=l"(d) : "l"(a), "l"(b)); return d;
}
__device__ __forceinline__ void up2(u64 v, float& lo, float& hi) {
    asm("mov.b64 {%0,%1},%2;" : "=f"(lo), "=f"(hi) : "l"(v));
}
__device__ __forceinline__ float sigm(float v) {
    return __fdividef(1.0f, 1.0f + __expf(-v));
}
__device__ __forceinline__ float tanh_(float v) {
    return 1.0f - __fdividef(2.0f, __expf(2.0f * v) + 1.0f);
}

// ---------------- cp.async helpers ----------------
__device__ __forceinline__ void cpa16(void* dst, const void* src) {
    u32 d = (u32)__cvta_generic_to_shared(dst);
    asm volatile("cp.async.cg.shared.global [%0], [%1], 16;\n" :: "r"(d), "l"(src));
}
__device__ __forceinline__ void cpcommit() { asm volatile("cp.async.commit_group;\n"); }
template <int N> __device__ __forceinline__ void cpwait() {
    asm volatile("cp.async.wait_group %0;\n" :: "n"(N));
}

// ---------------- cluster helpers ----------------
#define CLUSTER_ARRIVE() asm volatile("barrier.cluster.arrive.aligned;" ::: "memory")
#define CLUSTER_WAIT()   asm volatile("barrier.cluster.wait.aligned;" ::: "memory")

__device__ __forceinline__ u32 ctarank() {
    u32 r; asm("mov.u32 %0, %%cluster_ctarank;" : "=r"(r)); return r;
}
__device__ __forceinline__ void st_peer_u64(u32 laddr, u32 peer, u64 v) {
    u32 raddr;
    asm("mapa.shared::cluster.u32 %0, %1, %2;" : "=r"(raddr) : "r"(laddr), "r"(peer));
    asm volatile("st.shared::cluster.b64 [%0], %1;" :: "r"(raddr), "l"(v) : "memory");
}
__device__ __forceinline__ void st_peer_u32(u32 laddr, u32 peer, u32 v) {
    u32 raddr;
    asm("mapa.shared::cluster.u32 %0, %1, %2;" : "=r"(raddr) : "r"(laddr), "r"(peer));
    asm volatile("st.shared::cluster.b32 [%0], %1;" :: "r"(raddr), "r"(v) : "memory");
}
__device__ __forceinline__ u32 smem_u32(const void* p) {
    return (u32)__cvta_generic_to_shared(p);
}

// ---------------- device-global precomputed state ----------------
__device__ float g_A[NNODE * NNODE];
__device__ float g_fold1[6 * HIDD];
__device__ float g_c2[3 * HIDD];
__device__ __align__(16) float g_W2L[3 * HIDD * HIDD];

// ---------------- fused setup kernel ----------------
__global__ void setup_all(
    const int* __restrict__ ei, const float* __restrict__ ew,
    const float* Wz1, const float* bz1, const float* lzw1, const float* lzb1,
    const float* Wr1, const float* br1, const float* lrw1, const float* lrb1,
    const float* Wh1, const float* bh1, const float* lhw1, const float* lhb1,
    const float* Wz2, const float* bz2, const float* lzw2, const float* lzb2,
    const float* Wr2, const float* br2, const float* lrw2, const float* lrb2,
    const float* Wh2, const float* bh2, const float* lhw2, const float* lhb2) {
    int tid = threadIdx.x;
    if (blockIdx.x == 0) {
        __shared__ float dinv[NNODE];
        if (tid < NNODE) {
            float d = 1.0f;
            for (int e = 0; e < NEDGE; e++)
                if (ei[NEDGE + e] == tid) d += ew[e];
            dinv[tid] = (d > 0.f) ? (1.0f / sqrtf(d)) : 0.0f;
        }
        __syncthreads();
        if (tid < NNODE * NNODE) {
            int i = tid / NNODE, j = tid % NNODE;
            float a = (i == j) ? dinv[i] * dinv[i] : 0.0f;
            for (int e = 0; e < NEDGE; e++)
                if (ei[e] == j && ei[NEDGE + e] == i)
                    a += dinv[j] * ew[e] * dinv[i];
            g_A[tid] = a;
        }
        if (tid < HIDD) {
            const float* Ws[3] = {Wz1, Wr1, Wh1};
            const float* bs[3] = {bz1, br1, bh1};
            const float* ls[3] = {lzw1, lrw1, lhw1};
            const float* lb[3] = {lzb1, lrb1, lhb1};
            for (int g = 0; g < 3; g++) {
                float v = 0.f, c = 0.f;
                for (int q = 0; q < HIDD; q++) {
                    float l = ls[g][q * HIDD + tid];
                    v += Ws[g][q] * l;
                    c += bs[g][q] * l;
                }
                g_fold1[g * HIDD + tid] = v;
                g_fold1[(3 + g) * HIDD + tid] = c + lb[g][tid];
            }
            const float* b2[3] = {bz2, br2, bh2};
            const float* l2[3] = {lzw2, lrw2, lhw2};
            const float* p2[3] = {lzb2, lrb2, lhb2};
            for (int g = 0; g < 3; g++) {
                float c = 0.f;
                for (int q = 0; q < HIDD; q++) c += b2[g][q] * l2[g][q * HIDD + tid];
                g_c2[g * HIDD + tid] = c + p2[g][tid];
            }
        }
    } else {
        __shared__ float wrow[HIDD];
        int id = blockIdx.x - 1;
        int g = id >> 7, k = id & 127;
        const float* W = (g == 0) ? Wz2 : ((g == 1) ? Wr2 : Wh2);
        const float* L = (g == 0) ? lzw2 : ((g == 1) ? lrw2 : lhw2);
        if (tid < HIDD) wrow[tid] = W[k * HIDD + tid];
        __syncthreads();
        if (tid < HIDD) {
            float a = 0.f;
            for (int q = 0; q < HIDD; q++) a += wrow[q] * L[q * HIDD + tid];
            g_W2L[g * HIDD * HIDD + k * HIDD + tid] = a;
        }
    }
}

// ---------------- staging (prefetched one pass ahead; 512 threads) ----------------
template <int NM>
__device__ __forceinline__ void stage_chunk(float* buf, const float* G0, const float* G1,
                                            int c, int tid) {
    int e = tid * 4;
    int row = e >> 6, col = e & 63;
    long off = (long)(c * 32 + row) * HIDD + col;
    float* reg = buf + c * (NM * CHUNK_F);
    cpa16(reg + e, G0 + off);
    if (NM > 1) cpa16(reg + CHUNK_F + e, G1 + off);
}
template <int NM>
__device__ __forceinline__ void stage_pass(float* buf, const float* G0, const float* G1, int tid) {
#pragma unroll
    for (int c = 0; c < 4; c++) stage_chunk<NM>(buf, G0, G1, c, tid);
    cpcommit();
}

// ---------------- compute 32 k's from a staged chunk ----------------
template <int NM>
__device__ __forceinline__ void mm32(const float* __restrict__ S, int kbase,
                                     const float* __restrict__ B,
                                     int i0, int ui, u64 (&A)[NM][3][2]) {
#pragma unroll 2
    for (int k4 = 0; k4 < 8; k4++) {
        float sa[3][4];
#pragma unroll
        for (int r = 0; r < 3; r++) {
            float4 q = *reinterpret_cast<const float4*>(S + (i0 + r) * HSTR + kbase + k4 * 4);
            sa[r][0] = q.x; sa[r][1] = q.y; sa[r][2] = q.z; sa[r][3] = q.w;
        }
#pragma unroll
        for (int kk = 0; kk < 4; kk++) {
            int k = k4 * 4 + kk;
            ulonglong2 ua, ub;
            ua = *(reinterpret_cast<const ulonglong2*>(B) + k * 16 + ui);
            if (NM > 1) ub = *(reinterpret_cast<const ulonglong2*>(B + CHUNK_F) + k * 16 + ui);
#pragma unroll
            for (int r = 0; r < 3; r++) {
                u64 s = bc2(sa[r][kk]);
                A[0][r][0] = fma2(s, ua.x, A[0][r][0]);
                A[0][r][1] = fma2(s, ua.y, A[0][r][1]);
                if (NM > 1) {
                    A[1][r][0] = fma2(s, ub.x, A[1][r][0]);
                    A[1][r][1] = fma2(s, ub.y, A[1][r][1]);
                }
            }
        }
    }
}

// Split-k pass over 4 quarters (warps 0-3: k[0,32)... warps 12-15: k[96,128)).
// Single-round combine: quarters 1-3 write dedicated scratch regions, quarter 0 sums.
// After return, quarter-0 lanes (tid<128) hold the full k-sum in A.
template <int NM, int NMn>
__device__ __forceinline__ void run_pass(const float* __restrict__ S,
                                         const float* __restrict__ bufC,
                                         float* bufN, const float* Gn0, const float* Gn1,
                                         u64* scx, int tid, int kq, int i0, int ui,
                                         u64 (&A)[NM][3][2]) {
    cpwait<0>();       // this pass's weights were staged during the previous pass
    __syncthreads();   // #1: staged data + prev epilogue S-writes visible; prev scratch reads done
    mm32<NM>(S, kq * 32, bufC + kq * (NM * CHUNK_F), i0, ui, A);
    stage_pass<NMn>(bufN, Gn0, Gn1, tid);   // prefetch next pass's weights
    const int SSTR = NM * 6 + 1;
    if (kq != 0) {
        u64* scr = scx + (kq - 1) * SCREG + (tid & 127) * SSTR;
#pragma unroll
        for (int m = 0; m < NM; m++)
#pragma unroll
            for (int r = 0; r < 3; r++) {
                scr[m * 6 + r * 2] = A[m][r][0];
                scr[m * 6 + r * 2 + 1] = A[m][r][1];
            }
    }
    __syncthreads();   // #2: partials visible
    if (kq == 0) {
#pragma unroll
        for (int q = 0; q < 3; q++) {
            const u64* scr = scx + q * SCREG + tid * SSTR;
#pragma unroll
            for (int m = 0; m < NM; m++)
#pragma unroll
                for (int r = 0; r < 3; r++) {
                    A[m][r][0] = add2(A[m][r][0], scr[m * 6 + r * 2]);
                    A[m][r][1] = add2(A[m][r][1], scr[m * 6 + r * 2 + 1]);
                }
        }
    }
}

// A-mix over node range [j0,j1): acc += A[i,j] * M[j, local cols] (M stride ZSTR)
template <int NM>
__device__ __forceinline__ void amixN(const float* __restrict__ sA,
                                      const float* __restrict__ M0,
                                      const float* __restrict__ M1,
                                      int j0, int j1, int i0, int ui, u64 (&A)[NM][3][2]) {
    const ulonglong2* Ma = reinterpret_cast<const ulonglong2*>(M0);
    const ulonglong2* Mb = reinterpret_cast<const ulonglong2*>(M1);
    for (int j = j0; j < j1; j++) {
        ulonglong2 ma = Ma[j * (ZSTR / 4) + ui];
        ulonglong2 mb;
        if (NM > 1) mb = Mb[j * (ZSTR / 4) + ui];
#pragma unroll
        for (int r = 0; r < 3; r++) {
            u64 a = bc2(sA[(i0 + r) * NNODE + j]);
            A[0][r][0] = fma2(a, ma.x, A[0][r][0]);
            A[0][r][1] = fma2(a, ma.y, A[0][r][1]);
            if (NM > 1) {
                A[1][r][0] = fma2(a, mb.x, A[1][r][0]);
                A[1][r][1] = fma2(a, mb.y, A[1][r][1]);
            }
        }
    }
}

// ---------------- smem layout (floats) ----------------
#define BIG (NPAD * HSTR)            // 3168
#define ZBIG (NPAD * ZSTR)           // 1632
#define OFF_H1 0
#define OFF_H2 (OFF_H1 + BIG)
#define OFF_HR (OFF_H2 + BIG)
#define OFF_Z  (OFF_HR + BIG)
#define OFF_MA (OFF_Z + ZBIG)
#define OFF_MB (OFF_MA + ZBIG)
#define OFF_MC (OFF_MB + ZBIG)
#define OFF_A  (OFF_MC + ZBIG)       // 504 (24x21)
#define OFF_Y  (OFF_A + 504)         // 32 ([24] = peer partial scratch)
#define OFF_V  (OFF_Y + 32)          // 1152
#define OFF_W0 (OFF_V + 1152)        // 16384 (NM=2 buffer: P1,P3,P5)
#define OFF_W1 (OFF_W0 + 16384)      // 8192  (NM=1 buffer: P2,P4,P6)
#define OFF_SC (OFF_W1 + 8192)       // 9984  (scratch: 3 regions x 128 x 13 u64)
#define SMEM_FLOATS (OFF_SC + 9984)  // 52280 floats = 209120 B

__global__ void __launch_bounds__(NTHR, 1) __cluster_dims__(2, 1, 1) tgcn_main(
    const float* __restrict__ x,
    const float* __restrict__ Uz1, const float* __restrict__ Ur1, const float* __restrict__ Uh1,
    const float* __restrict__ Uz2, const float* __restrict__ Ur2, const float* __restrict__ Uh2,
    const float* __restrict__ clsw, const float* __restrict__ clsb,
    float* __restrict__ out) {
    extern __shared__ float sm[];
    float* sH1 = sm + OFF_H1;     // full 128-col state (global feature index)
    float* sH2 = sm + OFF_H2;
    float* sHR = sm + OFF_HR;
    float* sZ  = sm + OFF_Z;      // half-width, local cols, stride ZSTR
    float* sMa = sm + OFF_MA;
    float* sMb = sm + OFF_MB;
    float* sMc = sm + OFF_MC;
    float* sA  = sm + OFF_A;
    float* sy  = sm + OFF_Y;
    float* sv  = sm + OFF_V;
    float* sw0 = sm + OFF_W0;
    float* sw1 = sm + OFF_W1;
    u64*   scx = reinterpret_cast<u64*>(sm + OFF_SC);
    float* svz = sv,        *svr = sv + 128,  *svh = sv + 256;
    float* scz = sv + 384,  *scrb = sv + 512, *sch = sv + 640;
    float* sc2z = sv + 768, *sc2r = sv + 896, *sc2h = sv + 1024;

    const int tid = threadIdx.x;
    const u32 rank = ctarank(), peer = 1 - rank;
    const int b = blockIdx.x >> 1;
    const int w = tid >> 5, lane = tid & 31;
    const int kq = w >> 2;              // k-quarter: warps 4q..4q+3 own k[32q, 32q+32)
    const int wc = w & 3;               // col-warp (16 local cols each)
    const int fg = lane & 3, rg = lane >> 2;
    const int ui = wc * 4 + fg;         // local 16B unit, [0,16)
    const int f0 = ui * 4;              // local col [0,64)
    const int fgl = rank * FHALF + f0;  // global feature col
    const int i0 = rg * 3;              // 3 rows (rows 21-23 padding at rg==7)

    for (int i = tid; i < BIG; i += NTHR) { sH1[i] = 0.f; sH2[i] = 0.f; }
    for (int i = tid; i < 504; i += NTHR) sA[i] = (i < NNODE * NNODE) ? g_A[i] : 0.f;
    if (tid < 32) sy[tid] = 0.f;
    if (tid < HIDD)
        for (int g = 0; g < 9; g++)
            sv[g * 128 + tid] = (g < 6) ? g_fold1[g * 128 + tid] : g_c2[(g - 6) * 128 + tid];
    __syncthreads();
    CLUSTER_ARRIVE();                    // gen 0: init done

    float accS[12];
#pragma unroll
    for (int q = 0; q < 12; q++) accS[q] = 0.f;

    const float* xb = x + (size_t)b * TSTEPS * NNODE;
    const float* W2Lz = g_W2L + rank * FHALF;
    const float* W2Lr = g_W2L + HIDD * HIDD + rank * FHALF;
    const float* W2Lh = g_W2L + 2 * HIDD * HIDD + rank * FHALF;
    const float* Vz1 = Uz1 + rank * FHALF;
    const float* Vr1 = Ur1 + rank * FHALF;
    const float* Vh1 = Uh1 + rank * FHALF;
    const float* Vz2 = Uz2 + rank * FHALF;
    const float* Vr2 = Ur2 + rank * FHALF;
    const float* Vh2 = Uh2 + rank * FHALF;

    // amix node split across k-quarters: 5/5/5/6
    const int aj0 = kq * 5, aj1 = (kq == 3) ? NNODE : (kq * 5 + 5);

    stage_pass<2>(sw0, Vz1, Vr1, tid);   // prime: P1 weights

    for (int t = 0; t < TSTEPS; t++) {
        CLUSTER_WAIT();                  // peer finished prev step

        // y = A @ x_t (consumed after P1's internal barriers)
        if (tid < NNODE) {
            const float* xr = xb + t * NNODE;
            float a = 0.f;
#pragma unroll
            for (int j = 0; j < NNODE; j++) a += sA[tid * NNODE + j] * xr[j];
            sy[tid] = a;
        }

        // ---- P1: Z1, R1 (S = full H1); prefetch P2 (Vh1 -> sw1) ----
        {
            u64 A[2][3][2] = {};
            run_pass<2, 1>(sH1, sw0, sw1, Vh1, nullptr, scx, tid, kq, i0, ui, A);
            if (tid < 128) {
#pragma unroll
                for (int r = 0; r < 3; r++) {
                    int i = i0 + r; float yv = sy[i];
                    float v[4], q[4];
                    up2(A[0][r][0], v[0], v[1]); up2(A[0][r][1], v[2], v[3]);
                    up2(A[1][r][0], q[0], q[1]); up2(A[1][r][1], q[2], q[3]);
                    float4 h4 = *reinterpret_cast<const float4*>(sH1 + i * HSTR + fgl);
                    float h[4] = {h4.x, h4.y, h4.z, h4.w};
                    float zz[4], rr[4];
#pragma unroll
                    for (int c = 0; c < 4; c++) {
                        int f = fgl + c;
                        zz[c] = sigm(fmaf(yv, svz[f], scz[f]) + v[c]);
                        rr[c] = sigm(fmaf(yv, svr[f], scrb[f]) + q[c]) * h[c];
                    }
                    *reinterpret_cast<float4*>(sZ + i * ZSTR + f0) = make_float4(zz[0], zz[1], zz[2], zz[3]);
                    *reinterpret_cast<float4*>(sHR + i * HSTR + fgl) = make_float4(rr[0], rr[1], rr[2], rr[3]);
                    u32 la = smem_u32(sHR + i * HSTR + fgl);
                    st_peer_u64(la, peer, pk2(rr[0], rr[1]));
                    st_peer_u64(la + 8, peer, pk2(rr[2], rr[3]));
                }
            }
        }
        CLUSTER_ARRIVE();   // HR exchanged
        CLUSTER_WAIT();

        // ---- P2: Ht1 + blend into H1 (S = full HR); prefetch P3 (W2Lz,W2Lr -> sw0) ----
        {
            u64 A[1][3][2] = {};
            run_pass<1, 2>(sHR, sw1, sw0, W2Lz, W2Lr, scx, tid, kq, i0, ui, A);
            if (tid < 128) {
#pragma unroll
                for (int r = 0; r < 3; r++) {
                    int i = i0 + r; float yv = sy[i];
                    float v[4];
                    up2(A[0][r][0], v[0], v[1]); up2(A[0][r][1], v[2], v[3]);
                    float4 h4 = *reinterpret_cast<const float4*>(sH1 + i * HSTR + fgl);
                    float4 z4 = *reinterpret_cast<const float4*>(sZ + i * ZSTR + f0);
                    float h[4] = {h4.x, h4.y, h4.z, h4.w};
                    float z[4] = {z4.x, z4.y, z4.z, z4.w};
                    float nh[4];
#pragma unroll
                    for (int c = 0; c < 4; c++) {
                        int f = fgl + c;
                        float hh = tanh_(fmaf(yv, svh[f], sch[f]) + v[c]);
                        nh[c] = fmaf(z[c], h[c] - hh, hh);
                    }
                    *reinterpret_cast<float4*>(sH1 + i * HSTR + fgl) = make_float4(nh[0], nh[1], nh[2], nh[3]);
                    u32 la = smem_u32(sH1 + i * HSTR + fgl);
                    st_peer_u64(la, peer, pk2(nh[0], nh[1]));
                    st_peer_u64(la + 8, peer, pk2(nh[2], nh[3]));
                }
            }
        }
        CLUSTER_ARRIVE();   // H1 exchanged
        CLUSTER_WAIT();

        // ---- P3: Mz, Mr = H1 @ W2L{z,r}; prefetch P4 (W2Lh -> sw1) ----
        {
            u64 A[2][3][2] = {};
            run_pass<2, 1>(sH1, sw0, sw1, W2Lh, nullptr, scx, tid, kq, i0, ui, A);
            if (tid < 128) {
#pragma unroll
                for (int r = 0; r < 3; r++) {
                    int i = i0 + r;
                    float a[4], bq[4];
                    up2(A[0][r][0], a[0], a[1]); up2(A[0][r][1], a[2], a[3]);
                    up2(A[1][r][0], bq[0], bq[1]); up2(A[1][r][1], bq[2], bq[3]);
                    *reinterpret_cast<float4*>(sMa + i * ZSTR + f0) = make_float4(a[0], a[1], a[2], a[3]);
                    *reinterpret_cast<float4*>(sMb + i * ZSTR + f0) = make_float4(bq[0], bq[1], bq[2], bq[3]);
                }
            }
        }

        // ---- P4: Mh = H1 @ W2Lh; prefetch P5 (Vz2,Vr2 -> sw0) ----
        {
            u64 A[1][3][2] = {};
            run_pass<1, 2>(sH1, sw1, sw0, Vz2, Vr2, scx, tid, kq, i0, ui, A);
            if (tid < 128) {
#pragma unroll
                for (int r = 0; r < 3; r++) {
                    int i = i0 + r;
                    float a[4];
                    up2(A[0][r][0], a[0], a[1]); up2(A[0][r][1], a[2], a[3]);
                    *reinterpret_cast<float4*>(sMc + i * ZSTR + f0) = make_float4(a[0], a[1], a[2], a[3]);
                }
            }
        }

        // ---- P5: Z2 / R2 (bias on kq0 + 4-way split amix + H2 matmul); prefetch P6 ----
        {
            u64 A[2][3][2];
            if (kq == 0) {
                u64 cz0 = pk2(sc2z[fgl], sc2z[fgl + 1]), cz1 = pk2(sc2z[fgl + 2], sc2z[fgl + 3]);
                u64 cr0 = pk2(sc2r[fgl], sc2r[fgl + 1]), cr1 = pk2(sc2r[fgl + 2], sc2r[fgl + 3]);
#pragma unroll
                for (int r = 0; r < 3; r++) {
                    A[0][r][0] = cz0; A[0][r][1] = cz1;
                    A[1][r][0] = cr0; A[1][r][1] = cr1;
                }
            } else {
#pragma unroll
                for (int r = 0; r < 3; r++) {
                    A[0][r][0] = 0; A[0][r][1] = 0;
                    A[1][r][0] = 0; A[1][r][1] = 0;
                }
            }
            amixN<2>(sA, sMa, sMb, aj0, aj1, i0, ui, A);
            run_pass<2, 1>(sH2, sw0, sw1, Vh2, nullptr, scx, tid, kq, i0, ui, A);
            if (tid < 128) {
#pragma unroll
                for (int r = 0; r < 3; r++) {
                    int i = i0 + r;
                    float v[4], q[4];
                    up2(A[0][r][0], v[0], v[1]); up2(A[0][r][1], v[2], v[3]);
                    up2(A[1][r][0], q[0], q[1]); up2(A[1][r][1], q[2], q[3]);
                    float4 h4 = *reinterpret_cast<const float4*>(sH2 + i * HSTR + fgl);
                    float h[4] = {h4.x, h4.y, h4.z, h4.w};
                    float zz[4], rr[4];
#pragma unroll
                    for (int c = 0; c < 4; c++) {
                        zz[c] = sigm(v[c]);
                        rr[c] = sigm(q[c]) * h[c];
                    }
                    *reinterpret_cast<float4*>(sZ + i * ZSTR + f0) = make_float4(zz[0], zz[1], zz[2], zz[3]);
                    *reinterpret_cast<float4*>(sHR + i * HSTR + fgl) = make_float4(rr[0], rr[1], rr[2], rr[3]);
                    u32 la = smem_u32(sHR + i * HSTR + fgl);
                    st_peer_u64(la, peer, pk2(rr[0], rr[1]));
                    st_peer_u64(la + 8, peer, pk2(rr[2], rr[3]));
                }
            }
        }
        CLUSTER_ARRIVE();   // HR2 exchanged
        CLUSTER_WAIT();

        // ---- P6: Ht2 + blend into H2 + output acc; prefetch NEXT STEP P1 ----
        {
            u64 A[1][3][2];
            if (kq == 0) {
                u64 ch0 = pk2(sc2h[fgl], sc2h[fgl + 1]), ch1 = pk2(sc2h[fgl + 2], sc2h[fgl + 3]);
#pragma unroll
                for (int r = 0; r < 3; r++) { A[0][r][0] = ch0; A[0][r][1] = ch1; }
            } else {
#pragma unroll
                for (int r = 0; r < 3; r++) { A[0][r][0] = 0; A[0][r][1] = 0; }
            }
            amixN<1>(sA, sMc, nullptr, aj0, aj1, i0, ui, A);
            run_pass<1, 2>(sHR, sw1, sw0, Vz1, Vr1, scx, tid, kq, i0, ui, A);
            if (tid < 128) {
#pragma unroll
                for (int r = 0; r < 3; r++) {
                    int i = i0 + r;
                    float v[4];
                    up2(A[0][r][0], v[0], v[1]); up2(A[0][r][1], v[2], v[3]);
                    float4 h4 = *reinterpret_cast<const float4*>(sH2 + i * HSTR + fgl);
                    float4 z4 = *reinterpret_cast<const float4*>(sZ + i * ZSTR + f0);
                    float h[4] = {h4.x, h4.y, h4.z, h4.w};
                    float z[4] = {z4.x, z4.y, z4.z, z4.w};
                    float nh[4];
#pragma unroll
                    for (int c = 0; c < 4; c++) {
                        float hh = tanh_(v[c]);
                        nh[c] = fmaf(z[c], h[c] - hh, hh);
                        if (rg < 7) accS[r * 4 + c] += nh[c];
                    }
                    *reinterpret_cast<float4*>(sH2 + i * HSTR + fgl) = make_float4(nh[0], nh[1], nh[2], nh[3]);
                    u32 la = smem_u32(sH2 + i * HSTR + fgl);
                    st_peer_u64(la, peer, pk2(nh[0], nh[1]));
                    st_peer_u64(la + 8, peer, pk2(nh[2], nh[3]));
                }
            }
        }
        CLUSTER_ARRIVE();   // H2 exchanged (consumed next step P5)
    }
    cpwait<0>();
    CLUSTER_WAIT();          // matches last arrive

    // ---- final: partial over own 64 features; combine across cluster ----
    __syncthreads();
    if (tid < 128 && rg < 7) {
        float cs[4];
#pragma unroll
        for (int c = 0; c < 4; c++) cs[c] = accS[c] + accS[4 + c] + accS[8 + c];
        *reinterpret_cast<float4*>(sMa + rg * FHALF + f0) = make_float4(cs[0], cs[1], cs[2], cs[3]);
    }
    __syncthreads();
    if (tid < FHALF) {
        float s = 0.f;
#pragma unroll
        for (int r = 0; r < 7; r++) s += sMa[r * FHALF + tid];
        s *= (1.0f / (float)(NNODE * TSTEPS));
        sMb[tid] = s * clsw[rank * FHALF + tid];
    }
    __syncthreads();
    float own = 0.f;
    if (tid == 0) {
        for (int f = 0; f < FHALF; f++) own += sMb[f];
        if (rank == 1) st_peer_u32(smem_u32(sy + 24), 0, __float_as_uint(own));
    }
    CLUSTER_ARRIVE();
    CLUSTER_WAIT();
    if (rank == 0 && tid == 0)
        out[b] = own + sy[24] + clsb[0];
}

// ---------------- launch ----------------
extern "C" void kernel_launch(void* const* d_in, const int* in_sizes, int n_in,
                              void* d_out, int out_size) {
    const float* x    = (const float*)d_in[0];
    const int*   ei   = (const int*)d_in[1];
    const float* ew   = (const float*)d_in[2];
    const float* Wz1  = (const float*)d_in[3];
    const float* bz1  = (const float*)d_in[4];
    const float* lzw1 = (const float*)d_in[5];
    const float* lzb1 = (const float*)d_in[6];
    const float* Wr1  = (const float*)d_in[7];
    const float* br1  = (const float*)d_in[8];
    const float* lrw1 = (const float*)d_in[9];
    const float* lrb1 = (const float*)d_in[10];
    const float* Wh1  = (const float*)d_in[11];
    const float* bh1  = (const float*)d_in[12];
    const float* lhw1 = (const float*)d_in[13];
    const float* lhb1 = (const float*)d_in[14];
    const float* Wz2  = (const float*)d_in[15];
    const float* bz2  = (const float*)d_in[16];
    const float* lzw2 = (const float*)d_in[17];
    const float* lzb2 = (const float*)d_in[18];
    const float* Wr2  = (const float*)d_in[19];
    const float* br2  = (const float*)d_in[20];
    const float* lrw2 = (const float*)d_in[21];
    const float* lrb2 = (const float*)d_in[22];
    const float* Wh2  = (const float*)d_in[23];
    const float* bh2  = (const float*)d_in[24];
    const float* lhw2 = (const float*)d_in[25];
    const float* lhb2 = (const float*)d_in[26];
    const float* clsw = (const float*)d_in[27];
    const float* clsb = (const float*)d_in[28];
    float* out = (float*)d_out;

    setup_all<<<385, 448>>>(ei, ew,
        Wz1, bz1, lzw1, lzb1, Wr1, br1, lrw1, lrb1, Wh1, bh1, lhw1, lhb1,
        Wz2, bz2, lzw2, lzb2, Wr2, br2, lrw2, lrb2, Wh2, bh2, lhw2, lhb2);

    const int smem_bytes = SMEM_FLOATS * (int)sizeof(float);  // 209120
    cudaFuncSetAttribute(tgcn_main, cudaFuncAttributeMaxDynamicSharedMemorySize, smem_bytes);
    tgcn_main<<<128, NTHR, smem_bytes>>>(
        x,
        lzw1 + HIDD * HIDD, lrw1 + HIDD * HIDD, lhw1 + HIDD * HIDD,
        lzw2 + HIDD * HIDD, lrw2 + HIDD * HIDD, lhw2 + HIDD * HIDD,
        clsw, clsb, out);
}

// round 16
// speedup vs baseline: 1.2744x; 1.0068x over previous
#include <cuda_runtime.h>
#include <cstdint>

#define NNODE 21
#define NPAD 24
#define HIDD 128
#define HSTR 132            // full-width state row stride (floats), conflict-free
#define ZSTR 68             // half-width array row stride (floats)
#define TSTEPS 500
#define NEDGE 210
#define NTHR 512
#define FHALF 64            // features per CTA (cluster of 2)
#define CHUNK_F 2048        // floats per 32-k x 64-col weight chunk
#define SCREG 1664          // u64 per scratch region (128 x 13)

typedef unsigned long long u64;
typedef unsigned int u32;

// ---------------- packed f32x2 helpers ----------------
__device__ __forceinline__ u64 pk2(float lo, float hi) {
    u64 r; asm("mov.b64 %0,{%1,%2};" : "=l"(r) : "f"(lo), "f"(hi)); return r;
}
__device__ __forceinline__ u64 bc2(float v) {
    u64 r; asm("mov.b64 %0,{%1,%1};" : "=l"(r) : "f"(v)); return r;
}
__device__ __forceinline__ u64 fma2(u64 a, u64 b, u64 c) {
    u64 d; asm("fma.rn.f32x2 %0,%1,%2,%3;" : "=l"(d) : "l"(a), "l"(b), "l"(c)); return d;
}
__device__ __forceinline__ u64 add2(u64 a, u64 b) {
    u64 d; asm("add.rn.f32x2 %0,%1,%2;" : "=l"(d) : "l"(a), "l"(b)); return d;
}
__device__ __forceinline__ void up2(u64 v, float& lo, float& hi) {
    asm("mov.b64 {%0,%1},%2;" : "=f"(lo), "=f"(hi) : "l"(v));
}
// gates via single-SFU tanh.approx (sm_75+); sigm(x) = 0.5*tanh(x/2) + 0.5
__device__ __forceinline__ float tanh_(float v) {
    float r; asm("tanh.approx.f32 %0, %1;" : "=f"(r) : "f"(v)); return r;
}
__device__ __forceinline__ float sigm(float v) {
    return fmaf(tanh_(0.5f * v), 0.5f, 0.5f);
}

// ---------------- cp.async helpers ----------------
__device__ __forceinline__ void cpa16(void* dst, const void* src) {
    u32 d = (u32)__cvta_generic_to_shared(dst);
    asm volatile("cp.async.cg.shared.global [%0], [%1], 16;\n" :: "r"(d), "l"(src));
}
__device__ __forceinline__ void cpcommit() { asm volatile("cp.async.commit_group;\n"); }
template <int N> __device__ __forceinline__ void cpwait() {
    asm volatile("cp.async.wait_group %0;\n" :: "n"(N));
}

// ---------------- cluster helpers ----------------
#define CLUSTER_ARRIVE() asm volatile("barrier.cluster.arrive.aligned;" ::: "memory")
#define CLUSTER_WAIT()   asm volatile("barrier.cluster.wait.aligned;" ::: "memory")

__device__ __forceinline__ u32 ctarank() {
    u32 r; asm("mov.u32 %0, %%cluster_ctarank;" : "=r"(r)); return r;
}
__device__ __forceinline__ u32 mapa_peer(u32 laddr, u32 peer) {
    u32 raddr;
    asm("mapa.shared::cluster.u32 %0, %1, %2;" : "=r"(raddr) : "r"(laddr), "r"(peer));
    return raddr;
}
__device__ __forceinline__ void st_cluster_u64(u32 raddr, u64 v) {
    asm volatile("st.shared::cluster.b64 [%0], %1;" :: "r"(raddr), "l"(v) : "memory");
}
__device__ __forceinline__ void st_cluster_u32(u32 raddr, u32 v) {
    asm volatile("st.shared::cluster.b32 [%0], %1;" :: "r"(raddr), "r"(v) : "memory");
}
__device__ __forceinline__ u32 smem_u32(const void* p) {
    return (u32)__cvta_generic_to_shared(p);
}

// ---------------- device-global precomputed state ----------------
__device__ float g_A[NNODE * NNODE];
__device__ float g_fold1[6 * HIDD];
__device__ float g_c2[3 * HIDD];
__device__ __align__(16) float g_W2L[3 * HIDD * HIDD];

// ---------------- fused setup kernel ----------------
__global__ void setup_all(
    const int* __restrict__ ei, const float* __restrict__ ew,
    const float* Wz1, const float* bz1, const float* lzw1, const float* lzb1,
    const float* Wr1, const float* br1, const float* lrw1, const float* lrb1,
    const float* Wh1, const float* bh1, const float* lhw1, const float* lhb1,
    const float* Wz2, const float* bz2, const float* lzw2, const float* lzb2,
    const float* Wr2, const float* br2, const float* lrw2, const float* lrb2,
    const float* Wh2, const float* bh2, const float* lhw2, const float* lhb2) {
    int tid = threadIdx.x;
    if (blockIdx.x == 0) {
        __shared__ float dinv[NNODE];
        if (tid < NNODE) {
            float d = 1.0f;
            for (int e = 0; e < NEDGE; e++)
                if (ei[NEDGE + e] == tid) d += ew[e];
            dinv[tid] = (d > 0.f) ? (1.0f / sqrtf(d)) : 0.0f;
        }
        __syncthreads();
        if (tid < NNODE * NNODE) {
            int i = tid / NNODE, j = tid % NNODE;
            float a = (i == j) ? dinv[i] * dinv[i] : 0.0f;
            for (int e = 0; e < NEDGE; e++)
                if (ei[e] == j && ei[NEDGE + e] == i)
                    a += dinv[j] * ew[e] * dinv[i];
            g_A[tid] = a;
        }
        if (tid < HIDD) {
            const float* Ws[3] = {Wz1, Wr1, Wh1};
            const float* bs[3] = {bz1, br1, bh1};
            const float* ls[3] = {lzw1, lrw1, lhw1};
            const float* lb[3] = {lzb1, lrb1, lhb1};
            for (int g = 0; g < 3; g++) {
                float v = 0.f, c = 0.f;
                for (int q = 0; q < HIDD; q++) {
                    float l = ls[g][q * HIDD + tid];
                    v += Ws[g][q] * l;
                    c += bs[g][q] * l;
                }
                g_fold1[g * HIDD + tid] = v;
                g_fold1[(3 + g) * HIDD + tid] = c + lb[g][tid];
            }
            const float* b2[3] = {bz2, br2, bh2};
            const float* l2[3] = {lzw2, lrw2, lhw2};
            const float* p2[3] = {lzb2, lrb2, lhb2};
            for (int g = 0; g < 3; g++) {
                float c = 0.f;
                for (int q = 0; q < HIDD; q++) c += b2[g][q] * l2[g][q * HIDD + tid];
                g_c2[g * HIDD + tid] = c + p2[g][tid];
            }
        }
    } else {
        __shared__ float wrow[HIDD];
        int id = blockIdx.x - 1;
        int g = id >> 7, k = id & 127;
        const float* W = (g == 0) ? Wz2 : ((g == 1) ? Wr2 : Wh2);
        const float* L = (g == 0) ? lzw2 : ((g == 1) ? lrw2 : lhw2);
        if (tid < HIDD) wrow[tid] = W[k * HIDD + tid];
        __syncthreads();
        if (tid < HIDD) {
            float a = 0.f;
            for (int q = 0; q < HIDD; q++) a += wrow[q] * L[q * HIDD + tid];
            g_W2L[g * HIDD * HIDD + k * HIDD + tid] = a;
        }
    }
}

// ---------------- staging (prefetched one pass ahead; 512 threads) ----------------
template <int NM>
__device__ __forceinline__ void stage_chunk(float* buf, const float* G0, const float* G1,
                                            int c, int tid) {
    int e = tid * 4;
    int row = e >> 6, col = e & 63;
    long off = (long)(c * 32 + row) * HIDD + col;
    float* reg = buf + c * (NM * CHUNK_F);
    cpa16(reg + e, G0 + off);
    if (NM > 1) cpa16(reg + CHUNK_F + e, G1 + off);
}
template <int NM>
__device__ __forceinline__ void stage_pass(float* buf, const float* G0, const float* G1, int tid) {
#pragma unroll
    for (int c = 0; c < 4; c++) stage_chunk<NM>(buf, G0, G1, c, tid);
    cpcommit();
}

// ---------------- compute 32 k's from a staged chunk ----------------
template <int NM>
__device__ __forceinline__ void mm32(const float* __restrict__ S, int kbase,
                                     const float* __restrict__ B,
                                     int i0, int ui, u64 (&A)[NM][3][2]) {
#pragma unroll 2
    for (int k4 = 0; k4 < 8; k4++) {
        float sa[3][4];
#pragma unroll
        for (int r = 0; r < 3; r++) {
            float4 q = *reinterpret_cast<const float4*>(S + (i0 + r) * HSTR + kbase + k4 * 4);
            sa[r][0] = q.x; sa[r][1] = q.y; sa[r][2] = q.z; sa[r][3] = q.w;
        }
#pragma unroll
        for (int kk = 0; kk < 4; kk++) {
            int k = k4 * 4 + kk;
            ulonglong2 ua, ub;
            ua = *(reinterpret_cast<const ulonglong2*>(B) + k * 16 + ui);
            if (NM > 1) ub = *(reinterpret_cast<const ulonglong2*>(B + CHUNK_F) + k * 16 + ui);
#pragma unroll
            for (int r = 0; r < 3; r++) {
                u64 s = bc2(sa[r][kk]);
                A[0][r][0] = fma2(s, ua.x, A[0][r][0]);
                A[0][r][1] = fma2(s, ua.y, A[0][r][1]);
                if (NM > 1) {
                    A[1][r][0] = fma2(s, ub.x, A[1][r][0]);
                    A[1][r][1] = fma2(s, ub.y, A[1][r][1]);
                }
            }
        }
    }
}

// Split-k pass over 4 quarters. Single-round combine: quarters 1-3 write dedicated
// scratch regions, quarter 0 sums. After return, tid<128 lanes hold the full k-sum.
template <int NM, int NMn>
__device__ __forceinline__ void run_pass(const float* __restrict__ S,
                                         const float* __restrict__ bufC,
                                         float* bufN, const float* Gn0, const float* Gn1,
                                         u64* scx, int tid, int kq, int i0, int ui,
                                         u64 (&A)[NM][3][2]) {
    cpwait<0>();       // this pass's weights were staged during the previous pass
    __syncthreads();   // #1: staged data + prev epilogue S-writes visible; prev scratch reads done
    mm32<NM>(S, kq * 32, bufC + kq * (NM * CHUNK_F), i0, ui, A);
    stage_pass<NMn>(bufN, Gn0, Gn1, tid);   // prefetch next pass's weights
    const int SSTR = NM * 6 + 1;
    if (kq != 0) {
        u64* scr = scx + (kq - 1) * SCREG + (tid & 127) * SSTR;
#pragma unroll
        for (int m = 0; m < NM; m++)
#pragma unroll
            for (int r = 0; r < 3; r++) {
                scr[m * 6 + r * 2] = A[m][r][0];
                scr[m * 6 + r * 2 + 1] = A[m][r][1];
            }
    }
    __syncthreads();   // #2: partials visible
    if (kq == 0) {
#pragma unroll
        for (int q = 0; q < 3; q++) {
            const u64* scr = scx + q * SCREG + tid * SSTR;
#pragma unroll
            for (int m = 0; m < NM; m++)
#pragma unroll
                for (int r = 0; r < 3; r++) {
                    A[m][r][0] = add2(A[m][r][0], scr[m * 6 + r * 2]);
                    A[m][r][1] = add2(A[m][r][1], scr[m * 6 + r * 2 + 1]);
                }
        }
    }
}

// A-mix over node range [j0,j1): acc += A[i,j] * M[j, local cols] (M stride ZSTR)
template <int NM>
__device__ __forceinline__ void amixN(const float* __restrict__ sA,
                                      const float* __restrict__ M0,
                                      const float* __restrict__ M1,
                                      int j0, int j1, int i0, int ui, u64 (&A)[NM][3][2]) {
    const ulonglong2* Ma = reinterpret_cast<const ulonglong2*>(M0);
    const ulonglong2* Mb = reinterpret_cast<const ulonglong2*>(M1);
    for (int j = j0; j < j1; j++) {
        ulonglong2 ma = Ma[j * (ZSTR / 4) + ui];
        ulonglong2 mb;
        if (NM > 1) mb = Mb[j * (ZSTR / 4) + ui];
#pragma unroll
        for (int r = 0; r < 3; r++) {
            u64 a = bc2(sA[(i0 + r) * NNODE + j]);
            A[0][r][0] = fma2(a, ma.x, A[0][r][0]);
            A[0][r][1] = fma2(a, ma.y, A[0][r][1]);
            if (NM > 1) {
                A[1][r][0] = fma2(a, mb.x, A[1][r][0]);
                A[1][r][1] = fma2(a, mb.y, A[1][r][1]);
            }
        }
    }
}

// ---------------- smem layout (floats) ----------------
#define BIG (NPAD * HSTR)            // 3168
#define ZBIG (NPAD * ZSTR)           // 1632
#define OFF_H1 0
#define OFF_H2 (OFF_H1 + BIG)
#define OFF_HR (OFF_H2 + BIG)
#define OFF_Z  (OFF_HR + BIG)
#define OFF_MA (OFF_Z + ZBIG)
#define OFF_MB (OFF_MA + ZBIG)
#define OFF_MC (OFF_MB + ZBIG)
#define OFF_A  (OFF_MC + ZBIG)       // 504 (24x21)
#define OFF_Y  (OFF_A + 504)         // 64 (sy double buffer: [0..20],[32..52]; [24]=peer scratch)
#define OFF_V  (OFF_Y + 64)          // 1152
#define OFF_W0 (OFF_V + 1152)        // 16384 (NM=2 buffer: P1,P3,P5)
#define OFF_W1 (OFF_W0 + 16384)      // 8192  (NM=1 buffer: P2,P4,P6)
#define OFF_SC (OFF_W1 + 8192)       // 9984  (scratch: 3 regions x 128 x 13 u64)
#define SMEM_FLOATS (OFF_SC + 9984)  // 52312 floats = 209248 B

__global__ void __launch_bounds__(NTHR, 1) __cluster_dims__(2, 1, 1) tgcn_main(
    const float* __restrict__ x,
    const float* __restrict__ Uz1, const float* __restrict__ Ur1, const float* __restrict__ Uh1,
    const float* __restrict__ Uz2, const float* __restrict__ Ur2, const float* __restrict__ Uh2,
    const float* __restrict__ clsw, const float* __restrict__ clsb,
    float* __restrict__ out) {
    extern __shared__ float sm[];
    float* sH1 = sm + OFF_H1;     // full 128-col state (global feature index)
    float* sH2 = sm + OFF_H2;
    float* sHR = sm + OFF_HR;
    float* sZ  = sm + OFF_Z;      // half-width, local cols, stride ZSTR
    float* sMa = sm + OFF_MA;
    float* sMb = sm + OFF_MB;
    float* sMc = sm + OFF_MC;
    float* sA  = sm + OFF_A;
    float* sy  = sm + OFF_Y;
    float* sv  = sm + OFF_V;
    float* sw0 = sm + OFF_W0;
    float* sw1 = sm + OFF_W1;
    u64*   scx = reinterpret_cast<u64*>(sm + OFF_SC);
    float* svz = sv,        *svr = sv + 128,  *svh = sv + 256;
    float* scz = sv + 384,  *scrb = sv + 512, *sch = sv + 640;
    float* sc2z = sv + 768, *sc2r = sv + 896, *sc2h = sv + 1024;

    const int tid = threadIdx.x;
    const u32 rank = ctarank(), peer = 1 - rank;
    const int b = blockIdx.x >> 1;
    const int w = tid >> 5, lane = tid & 31;
    const int kq = w >> 2;              // k-quarter: warps 4q..4q+3 own k[32q, 32q+32)
    const int wc = w & 3;               // col-warp (16 local cols each)
    const int fg = lane & 3, rg = lane >> 2;
    const int ui = wc * 4 + fg;         // local 16B unit, [0,16)
    const int f0 = ui * 4;              // local col [0,64)
    const int fgl = rank * FHALF + f0;  // global feature col
    const int i0 = rg * 3;              // 3 rows (rows 21-23 padding at rg==7)

    // hoisted DSMEM remote bases (aperture is linear: remote = mapa(base) + offset)
    const u32 rHR = mapa_peer(smem_u32(sHR), peer);
    const u32 rH1 = mapa_peer(smem_u32(sH1), peer);
    const u32 rH2 = mapa_peer(smem_u32(sH2), peer);
    const u32 eoff = (u32)(fgl * 4);    // byte offset of this lane's 4-col group within a row

    for (int i = tid; i < BIG; i += NTHR) { sH1[i] = 0.f; sH2[i] = 0.f; }
    for (int i = tid; i < 504; i += NTHR) sA[i] = (i < NNODE * NNODE) ? g_A[i] : 0.f;
    if (tid < 64) sy[tid] = 0.f;
    if (tid < HIDD)
        for (int g = 0; g < 9; g++)
            sv[g * 128 + tid] = (g < 6) ? g_fold1[g * 128 + tid] : g_c2[(g - 6) * 128 + tid];
    __syncthreads();

    const float* xb = x + (size_t)b * TSTEPS * NNODE;
    // prime sy[buf 0] = A @ x_0
    if (tid < NNODE) {
        float a = 0.f;
#pragma unroll
        for (int j = 0; j < NNODE; j++) a += sA[tid * NNODE + j] * xb[j];
        sy[tid] = a;
    }
    CLUSTER_ARRIVE();                    // gen 0: init done

    float accS[12];
#pragma unroll
    for (int q = 0; q < 12; q++) accS[q] = 0.f;

    const float* W2Lz = g_W2L + rank * FHALF;
    const float* W2Lr = g_W2L + HIDD * HIDD + rank * FHALF;
    const float* W2Lh = g_W2L + 2 * HIDD * HIDD + rank * FHALF;
    const float* Vz1 = Uz1 + rank * FHALF;
    const float* Vr1 = Ur1 + rank * FHALF;
    const float* Vh1 = Uh1 + rank * FHALF;
    const float* Vz2 = Uz2 + rank * FHALF;
    const float* Vr2 = Ur2 + rank * FHALF;
    const float* Vh2 = Uh2 + rank * FHALF;

    // amix node split across k-quarters: 5/5/5/6
    const int aj0 = kq * 5, aj1 = (kq == 3) ? NNODE : (kq * 5 + 5);

    stage_pass<2>(sw0, Vz1, Vr1, tid);   // prime: P1 weights

    for (int t = 0; t < TSTEPS; t++) {
        CLUSTER_WAIT();                  // peer finished prev step
        const float* syc = sy + (t & 1) * 32;       // current step's A@x_t (pre-staged)
        float* syn = sy + ((t + 1) & 1) * 32;       // next step's buffer

        // ---- P1: Z1, R1 (S = full H1); prefetch P2 (Vh1 -> sw1) ----
        {
            u64 A[2][3][2] = {};
            run_pass<2, 1>(sH1, sw0, sw1, Vh1, nullptr, scx, tid, kq, i0, ui, A);
            if (tid < 128) {
#pragma unroll
                for (int r = 0; r < 3; r++) {
                    int i = i0 + r; float yv = syc[i];
                    float v[4], q[4];
                    up2(A[0][r][0], v[0], v[1]); up2(A[0][r][1], v[2], v[3]);
                    up2(A[1][r][0], q[0], q[1]); up2(A[1][r][1], q[2], q[3]);
                    float4 h4 = *reinterpret_cast<const float4*>(sH1 + i * HSTR + fgl);
                    float h[4] = {h4.x, h4.y, h4.z, h4.w};
                    float zz[4], rr[4];
#pragma unroll
                    for (int c = 0; c < 4; c++) {
                        int f = fgl + c;
                        zz[c] = sigm(fmaf(yv, svz[f], scz[f]) + v[c]);
                        rr[c] = sigm(fmaf(yv, svr[f], scrb[f]) + q[c]) * h[c];
                    }
                    *reinterpret_cast<float4*>(sZ + i * ZSTR + f0) = make_float4(zz[0], zz[1], zz[2], zz[3]);
                    *reinterpret_cast<float4*>(sHR + i * HSTR + fgl) = make_float4(rr[0], rr[1], rr[2], rr[3]);
                    u32 ra = rHR + (u32)(i * HSTR * 4) + eoff;
                    st_cluster_u64(ra, pk2(rr[0], rr[1]));
                    st_cluster_u64(ra + 8, pk2(rr[2], rr[3]));
                }
            }
            // stage next step's sy (x LDG latency hidden under P2..P6)
            if (tid >= 128 && tid < 128 + NNODE && t + 1 < TSTEPS) {
                int n = tid - 128;
                const float* xr = xb + (t + 1) * NNODE;
                float a = 0.f;
#pragma unroll
                for (int j = 0; j < NNODE; j++) a += sA[n * NNODE + j] * xr[j];
                syn[n] = a;
            }
        }
        CLUSTER_ARRIVE();   // HR exchanged
        CLUSTER_WAIT();

        // ---- P2: Ht1 + blend into H1 (S = full HR); prefetch P3 (W2Lz,W2Lr -> sw0) ----
        {
            u64 A[1][3][2] = {};
            run_pass<1, 2>(sHR, sw1, sw0, W2Lz, W2Lr, scx, tid, kq, i0, ui, A);
            if (tid < 128) {
#pragma unroll
                for (int r = 0; r < 3; r++) {
                    int i = i0 + r; float yv = syc[i];
                    float v[4];
                    up2(A[0][r][0], v[0], v[1]); up2(A[0][r][1], v[2], v[3]);
                    float4 h4 = *reinterpret_cast<const float4*>(sH1 + i * HSTR + fgl);
                    float4 z4 = *reinterpret_cast<const float4*>(sZ + i * ZSTR + f0);
                    float h[4] = {h4.x, h4.y, h4.z, h4.w};
                    float z[4] = {z4.x, z4.y, z4.z, z4.w};
                    float nh[4];
#pragma unroll
                    for (int c = 0; c < 4; c++) {
                        int f = fgl + c;
                        float hh = tanh_(fmaf(yv, svh[f], sch[f]) + v[c]);
                        nh[c] = fmaf(z[c], h[c] - hh, hh);
                    }
                    *reinterpret_cast<float4*>(sH1 + i * HSTR + fgl) = make_float4(nh[0], nh[1], nh[2], nh[3]);
                    u32 ra = rH1 + (u32)(i * HSTR * 4) + eoff;
                    st_cluster_u64(ra, pk2(nh[0], nh[1]));
                    st_cluster_u64(ra + 8, pk2(nh[2], nh[3]));
                }
            }
        }
        CLUSTER_ARRIVE();   // H1 exchanged
        CLUSTER_WAIT();

        // ---- P3: Mz, Mr = H1 @ W2L{z,r}; prefetch P4 (W2Lh -> sw1) ----
        {
            u64 A[2][3][2] = {};
            run_pass<2, 1>(sH1, sw0, sw1, W2Lh, nullptr, scx, tid, kq, i0, ui, A);
            if (tid < 128) {
#pragma unroll
                for (int r = 0; r < 3; r++) {
                    int i = i0 + r;
                    float a[4], bq[4];
                    up2(A[0][r][0], a[0], a[1]); up2(A[0][r][1], a[2], a[3]);
                    up2(A[1][r][0], bq[0], bq[1]); up2(A[1][r][1], bq[2], bq[3]);
                    *reinterpret_cast<float4*>(sMa + i * ZSTR + f0) = make_float4(a[0], a[1], a[2], a[3]);
                    *reinterpret_cast<float4*>(sMb + i * ZSTR + f0) = make_float4(bq[0], bq[1], bq[2], bq[3]);
                }
            }
        }

        // ---- P4: Mh = H1 @ W2Lh; prefetch P5 (Vz2,Vr2 -> sw0) ----
        {
            u64 A[1][3][2] = {};
            run_pass<1, 2>(sH1, sw1, sw0, Vz2, Vr2, scx, tid, kq, i0, ui, A);
            if (tid < 128) {
#pragma unroll
                for (int r = 0; r < 3; r++) {
                    int i = i0 + r;
                    float a[4];
                    up2(A[0][r][0], a[0], a[1]); up2(A[0][r][1], a[2], a[3]);
                    *reinterpret_cast<float4*>(sMc + i * ZSTR + f0) = make_float4(a[0], a[1], a[2], a[3]);
                }
            }
        }

        // ---- P5: Z2 / R2 (bias on kq0 + 4-way split amix + H2 matmul); prefetch P6 ----
        {
            u64 A[2][3][2];
            if (kq == 0) {
                u64 cz0 = pk2(sc2z[fgl], sc2z[fgl + 1]), cz1 = pk2(sc2z[fgl + 2], sc2z[fgl + 3]);
                u64 cr0 = pk2(sc2r[fgl], sc2r[fgl + 1]), cr1 = pk2(sc2r[fgl + 2], sc2r[fgl + 3]);
#pragma unroll
                for (int r = 0; r < 3; r++) {
                    A[0][r][0] = cz0; A[0][r][1] = cz1;
                    A[1][r][0] = cr0; A[1][r][1] = cr1;
                }
            } else {
#pragma unroll
                for (int r = 0; r < 3; r++) {
                    A[0][r][0] = 0; A[0][r][1] = 0;
                    A[1][r][0] = 0; A[1][r][1] = 0;
                }
            }
            amixN<2>(sA, sMa, sMb, aj0, aj1, i0, ui, A);
            run_pass<2, 1>(sH2, sw0, sw1, Vh2, nullptr, scx, tid, kq, i0, ui, A);
            if (tid < 128) {
#pragma unroll
                for (int r = 0; r < 3; r++) {
                    int i = i0 + r;
                    float v[4], q[4];
                    up2(A[0][r][0], v[0], v[1]); up2(A[0][r][1], v[2], v[3]);
                    up2(A[1][r][0], q[0], q[1]); up2(A[1][r][1], q[2], q[3]);
                    float4 h4 = *reinterpret_cast<const float4*>(sH2 + i * HSTR + fgl);
                    float h[4] = {h4.x, h4.y, h4.z, h4.w};
                    float zz[4], rr[4];
#pragma unroll
                    for (int c = 0; c < 4; c++) {
                        zz[c] = sigm(v[c]);
                        rr[c] = sigm(q[c]) * h[c];
                    }
                    *reinterpret_cast<float4*>(sZ + i * ZSTR + f0) = make_float4(zz[0], zz[1], zz[2], zz[3]);
                    *reinterpret_cast<float4*>(sHR + i * HSTR + fgl) = make_float4(rr[0], rr[1], rr[2], rr[3]);
                    u32 ra = rHR + (u32)(i * HSTR * 4) + eoff;
                    st_cluster_u64(ra, pk2(rr[0], rr[1]));
                    st_cluster_u64(ra + 8, pk2(rr[2], rr[3]));
                }
            }
        }
        CLUSTER_ARRIVE();   // HR2 exchanged
        CLUSTER_WAIT();

        // ---- P6: Ht2 + blend into H2 + output acc; prefetch NEXT STEP P1 ----
        {
            u64 A[1][3][2];
            if (kq == 0) {
                u64 ch0 = pk2(sc2h[fgl], sc2h[fgl + 1]), ch1 = pk2(sc2h[fgl + 2], sc2h[fgl + 3]);
#pragma unroll
                for (int r = 0; r < 3; r++) { A[0][r][0] = ch0; A[0][r][1] = ch1; }
            } else {
#pragma unroll
                for (int r = 0; r < 3; r++) { A[0][r][0] = 0; A[0][r][1] = 0; }
            }
            amixN<1>(sA, sMc, nullptr, aj0, aj1, i0, ui, A);
            run_pass<1, 2>(sHR, sw1, sw0, Vz1, Vr1, scx, tid, kq, i0, ui, A);
            if (tid < 128) {
#pragma unroll
                for (int r = 0; r < 3; r++) {
                    int i = i0 + r;
                    float v[4];
                    up2(A[0][r][0], v[0], v[1]); up2(A[0][r][1], v[2], v[3]);
                    float4 h4 = *reinterpret_cast<const float4*>(sH2 + i * HSTR + fgl);
                    float4 z4 = *reinterpret_cast<const float4*>(sZ + i * ZSTR + f0);
                    float h[4] = {h4.x, h4.y, h4.z, h4.w};
                    float z[4] = {z4.x, z4.y, z4.z, z4.w};
                    float nh[4];
#pragma unroll
                    for (int c = 0; c < 4; c++) {
                        float hh = tanh_(v[c]);
                        nh[c] = fmaf(z[c], h[c] - hh, hh);
                        if (rg < 7) accS[r * 4 + c] += nh[c];
                    }
                    *reinterpret_cast<float4*>(sH2 + i * HSTR + fgl) = make_float4(nh[0], nh[1], nh[2], nh[3]);
                    u32 ra = rH2 + (u32)(i * HSTR * 4) + eoff;
                    st_cluster_u64(ra, pk2(nh[0], nh[1]));
                    st_cluster_u64(ra + 8, pk2(nh[2], nh[3]));
                }
            }
        }
        CLUSTER_ARRIVE();   // H2 exchanged (consumed next step P5)
    }
    cpwait<0>();
    CLUSTER_WAIT();          // matches last arrive

    // ---- final: partial over own 64 features; combine across cluster ----
    __syncthreads();
    if (tid < 128 && rg < 7) {
        float cs[4];
#pragma unroll
        for (int c = 0; c < 4; c++) cs[c] = accS[c] + accS[4 + c] + accS[8 + c];
        *reinterpret_cast<float4*>(sMa + rg * FHALF + f0) = make_float4(cs[0], cs[1], cs[2], cs[3]);
    }
    __syncthreads();
    if (tid < FHALF) {
        float s = 0.f;
#pragma unroll
        for (int r = 0; r < 7; r++) s += sMa[r * FHALF + tid];
        s *= (1.0f / (float)(NNODE * TSTEPS));
        sMb[tid] = s * clsw[rank * FHALF + tid];
    }
    __syncthreads();
    float own = 0.f;
    if (tid == 0) {
        for (int f = 0; f < FHALF; f++) own += sMb[f];
        if (rank == 1) st_cluster_u32(mapa_peer(smem_u32(sy + 24), 0), __float_as_uint(own));
    }
    CLUSTER_ARRIVE();
    CLUSTER_WAIT();
    if (rank == 0 && tid == 0)
        out[b] = own + sy[24] + clsb[0];
}

// ---------------- launch ----------------
extern "C" void kernel_launch(void* const* d_in, const int* in_sizes, int n_in,
                              void* d_out, int out_size) {
    const float* x    = (const float*)d_in[0];
    const int*   ei   = (const int*)d_in[1];
    const float* ew   = (const float*)d_in[2];
    const float* Wz1  = (const float*)d_in[3];
    const float* bz1  = (const float*)d_in[4];
    const float* lzw1 = (const float*)d_in[5];
    const float* lzb1 = (const float*)d_in[6];
    const float* Wr1  = (const float*)d_in[7];
    const float* br1  = (const float*)d_in[8];
    const float* lrw1 = (const float*)d_in[9];
    const float* lrb1 = (const float*)d_in[10];
    const float* Wh1  = (const float*)d_in[11];
    const float* bh1  = (const float*)d_in[12];
    const float* lhw1 = (const float*)d_in[13];
    const float* lhb1 = (const float*)d_in[14];
    const float* Wz2  = (const float*)d_in[15];
    const float* bz2  = (const float*)d_in[16];
    const float* lzw2 = (const float*)d_in[17];
    const float* lzb2 = (const float*)d_in[18];
    const float* Wr2  = (const float*)d_in[19];
    const float* br2  = (const float*)d_in[20];
    const float* lrw2 = (const float*)d_in[21];
    const float* lrb2 = (const float*)d_in[22];
    const float* Wh2  = (const float*)d_in[23];
    const float* bh2  = (const float*)d_in[24];
    const float* lhw2 = (const float*)d_in[25];
    const float* lhb2 = (const float*)d_in[26];
    const float* clsw = (const float*)d_in[27];
    const float* clsb = (const float*)d_in[28];
    float* out = (float*)d_out;

    setup_all<<<385, 448>>>(ei, ew,
        Wz1, bz1, lzw1, lzb1, Wr1, br1, lrw1, lrb1, Wh1, bh1, lhw1, lhb1,
        Wz2, bz2, lzw2, lzb2, Wr2, br2, lrw2, lrb2, Wh2, bh2, lhw2, lhb2);

    const int smem_bytes = SMEM_FLOATS * (int)sizeof(float);  // 209248
    cudaFuncSetAttribute(tgcn_main, cudaFuncAttributeMaxDynamicSharedMemorySize, smem_bytes);
    tgcn_main<<<128, NTHR, smem_bytes>>>(
        x,
        lzw1 + HIDD * HIDD, lrw1 + HIDD * HIDD, lhw1 + HIDD * HIDD,
        lzw2 + HIDD * HIDD, lrw2 + HIDD * HIDD, lhw2 + HIDD * HIDD,
        clsw, clsb, out);
}